// round 10
// baseline (speedup 1.0000x reference)
#include <cuda_runtime.h>
#include <cuda_bf16.h>
#include <math.h>
#include <stdint.h>

#define N_WAY     100
#define K_SHOT    10
#define N_SUPPORT 1000
#define N_QUERY   8192
#define F_IN      4096
#define D_EMB     1024
#define EPS_F     1e-6f

#define M_TOT     9216   // 8192 query rows + 1000 support + 24 pad

// ---------------- scratch (static device globals; no allocations) ----------
__device__ __nv_bfloat16 g_Ahi[(size_t)M_TOT * F_IN];
__device__ __nv_bfloat16 g_Alo[(size_t)M_TOT * F_IN];
__device__ __nv_bfloat16 g_Wthi[(size_t)D_EMB * F_IN];
__device__ __nv_bfloat16 g_Wtlo[(size_t)D_EMB * F_IN];
__device__ float g_Z[(size_t)M_TOT * D_EMB];
__device__ float g_proto[128 * D_EMB];
__device__ float g_p2[128];
__device__ float g_ps[128];
__device__ float g_q2[N_QUERY];
__device__ float g_qs[N_QUERY];

// ======================= portable PTX helpers ==============================
__device__ __forceinline__ uint32_t smem_u32(const void* p) {
    uint32_t a;
    asm("{ .reg .u64 t; cvta.to.shared.u64 t, %1; cvt.u32.u64 %0, t; }"
        : "=r"(a) : "l"(p));
    return a;
}
__device__ __forceinline__ void cp_async16(uint32_t dst, const void* src) {
    asm volatile("cp.async.cg.shared.global [%0], [%1], 16;"
                 :: "r"(dst), "l"(src) : "memory");
}
__device__ __forceinline__ void cp_commit() {
    asm volatile("cp.async.commit_group;" ::: "memory");
}
__device__ __forceinline__ void cp_wait1() {
    asm volatile("cp.async.wait_group 1;" ::: "memory");
}
__device__ __forceinline__ void ldmx4(uint32_t* r, uint32_t addr) {
    asm volatile("ldmatrix.sync.aligned.m8n8.x4.shared.b16 {%0,%1,%2,%3}, [%4];"
                 : "=r"(r[0]), "=r"(r[1]), "=r"(r[2]), "=r"(r[3]) : "r"(addr));
}
__device__ __forceinline__ void mma_bf16(float* c, const uint32_t* a, const uint32_t* b) {
    asm volatile(
        "mma.sync.aligned.m16n8k16.row.col.f32.bf16.bf16.f32 "
        "{%0,%1,%2,%3}, {%4,%5,%6,%7}, {%8,%9}, {%0,%1,%2,%3};"
        : "+f"(c[0]), "+f"(c[1]), "+f"(c[2]), "+f"(c[3])
        : "r"(a[0]), "r"(a[1]), "r"(a[2]), "r"(a[3]), "r"(b[0]), "r"(b[1]));
}

// =====================================================================
// Kernel A: split fp32 inputs into bf16 hi/lo
// =====================================================================
__global__ void convert_A(const float* __restrict__ q, const float* __restrict__ s)
{
    size_t i = (size_t)blockIdx.x * blockDim.x + threadIdx.x;
    const size_t total = (size_t)M_TOT * F_IN / 4;
    if (i >= total) return;
    const size_t row = i / (F_IN / 4);
    const size_t seg = i % (F_IN / 4);
    float4 v;
    if (row < N_QUERY)                  v = *(const float4*)(q + row * F_IN + seg * 4);
    else if (row < N_QUERY + N_SUPPORT) v = *(const float4*)(s + (row - N_QUERY) * F_IN + seg * 4);
    else                                v = make_float4(0.f, 0.f, 0.f, 0.f);

    float x[4] = {v.x, v.y, v.z, v.w};
    union B4 { __nv_bfloat16 b[4]; uint2 u; } uh, ul;
    #pragma unroll
    for (int j = 0; j < 4; j++) {
        __nv_bfloat16 h = __float2bfloat16_rn(x[j]);
        uh.b[j] = h;
        ul.b[j] = __float2bfloat16_rn(x[j] - __bfloat162float(h));
    }
    *(uint2*)(g_Ahi + i * 4) = uh.u;
    *(uint2*)(g_Alo + i * 4) = ul.u;
}

// =====================================================================
// Kernel B: transpose W [4096,1024] -> Wt hi/lo [1024,4096] bf16
// =====================================================================
__global__ void convert_W(const float* __restrict__ W)
{
    __shared__ __nv_bfloat16 th[32][33];
    __shared__ __nv_bfloat16 tl[32][33];
    const int k0 = blockIdx.x * 32, n0 = blockIdx.y * 32;
    const int tx = threadIdx.x, ty = threadIdx.y;   // (32, 8)
    #pragma unroll
    for (int i = 0; i < 4; i++) {
        const int kk = ty + i * 8;
        float x = W[(size_t)(k0 + kk) * D_EMB + n0 + tx];
        __nv_bfloat16 h = __float2bfloat16_rn(x);
        th[kk][tx] = h;
        tl[kk][tx] = __float2bfloat16_rn(x - __bfloat162float(h));
    }
    __syncthreads();
    #pragma unroll
    for (int i = 0; i < 4; i++) {
        const int nn = ty + i * 8;
        g_Wthi[(size_t)(n0 + nn) * F_IN + k0 + tx] = th[tx][nn];
        g_Wtlo[(size_t)(n0 + nn) * F_IN + k0 + tx] = tl[tx][nn];
    }
}

// =====================================================================
// Kernel C: bf16x3 tensor-core GEMM, 128x256 tile, 8 warps (64x64),
// GK=32, 3-stage cp.async. Mainloop uses a 4-buffer ROLLING fragment
// pipeline: each LDSM batch (except the post-barrier one) is issued
// under the preceding 32-HMMA burst, keeping the tensor pipe fed.
// =====================================================================
#define GM 128
#define GN 256
#define GK 32
#define NCH (F_IN / GK)          // 128
#define ROWB 80                  // 32 bf16 + 8 pad bytes
#define SA_HI 0
#define SA_LO (GM * ROWB)                      // 10240
#define SB_HI (2 * GM * ROWB)                  // 20480
#define STAGE (2 * GM * ROWB + 2 * GN * ROWB)  // 61440
#define NSTAGE 3
#define GEMM_SMEM (NSTAGE * STAGE)             // 184320

__device__ __forceinline__ void copy_chunk(uint32_t sb, int blockRow, int blockCol,
                                           int c, int tid)
{
    const size_t kc = (size_t)c * GK;
    #pragma unroll
    for (int i = 0; i < 4; i++) {
        const int id  = tid + i * 256;
        const int arr = id >> 9;
        const int rid = (id >> 2) & 127;
        const int seg = id & 3;
        const char* src = (const char*)(arr ? g_Alo : g_Ahi)
                        + ((size_t)(blockRow + rid) * F_IN + kc) * 2 + seg * 16;
        cp_async16(sb + arr * (GM * ROWB) + rid * ROWB + seg * 16, src);
    }
    #pragma unroll
    for (int i = 0; i < 8; i++) {
        const int id  = tid + i * 256;
        const int arr = id >> 10;
        const int rid = (id >> 2) & 255;
        const int seg = id & 3;
        const char* src = (const char*)(arr ? g_Wtlo : g_Wthi)
                        + ((size_t)(blockCol + rid) * F_IN + kc) * 2 + seg * 16;
        cp_async16(sb + SB_HI + arr * (GN * ROWB) + rid * ROWB + seg * 16, src);
    }
}

// one full pass over the 64x64 warp tile: 32 HMMA
#define MMA_PASS(ACC, A, B)                                   \
    _Pragma("unroll")                                         \
    for (int mt = 0; mt < 4; mt++) {                          \
        _Pragma("unroll")                                     \
        for (int p = 0; p < 4; p++) {                         \
            mma_bf16(ACC[mt][p * 2 + 0], A[mt], &B[p][0]);    \
            mma_bf16(ACC[mt][p * 2 + 1], A[mt], &B[p][2]);    \
        }                                                     \
    }

#define LOAD_A(F, st, base, kb)                                           \
    _Pragma("unroll")                                                     \
    for (int mt = 0; mt < 4; mt++)                                        \
        ldmx4(F[mt], (st) + aOff + (base) + mt * (16 * ROWB) + (kb));

#define LOAD_B(F, st, arrOff, kb)                                         \
    _Pragma("unroll")                                                     \
    for (int p = 0; p < 4; p++)                                           \
        ldmx4(F[p], (st) + bOff[p] + (arrOff) + (kb));

__global__ __launch_bounds__(256, 1)
void gemm_bf16x3(const float* __restrict__ bias)
{
    extern __shared__ char smem[];
    const uint32_t sbase = smem_u32(smem);
    const int tid = threadIdx.x;
    const int wid = tid >> 5;
    const int l   = tid & 31;
    const int warpM = wid >> 2;          // 0..1 -> 64-row strip
    const int warpN = wid & 3;           // 0..3 -> 64-col strip
    const int blockRow = blockIdx.y * GM;
    const int blockCol = blockIdx.x * GN;

    const uint32_t aOff = (uint32_t)((warpM * 64 + (l & 15)) * ROWB + (l >> 4) * 16);
    uint32_t bOff[4];
    #pragma unroll
    for (int p = 0; p < 4; p++)
        bOff[p] = (uint32_t)(SB_HI + (warpN * 64 + p * 16 + ((l >> 4) & 1) * 8 + (l & 7)) * ROWB
                             + ((l >> 3) & 1) * 16);

    float acc[4][8][4];
    #pragma unroll
    for (int mt = 0; mt < 4; mt++)
        #pragma unroll
        for (int nt = 0; nt < 8; nt++)
            #pragma unroll
            for (int r = 0; r < 4; r++) acc[mt][nt][r] = 0.f;

    copy_chunk(sbase, blockRow, blockCol, 0, tid);
    cp_commit();
    copy_chunk(sbase + STAGE, blockRow, blockCol, 1, tid);
    cp_commit();

    uint32_t stOff = 0;
    uint32_t wrOff = 2 * STAGE;

    // 4 rolling fragment buffers (64 regs total)
    uint32_t A0[4][4], A1[4][4], B0[4][4], B1[4][4];

    for (int c = 0; c < NCH; c++) {
        cp_wait1();
        __syncthreads();

        if (c + 2 < NCH) copy_chunk(sbase + wrOff, blockRow, blockCol, c + 2, tid);
        cp_commit();

        const uint32_t st = sbase + stOff;

        // ---- explicit 4-buffer pipeline over the 6 passes of this chunk ----
        // passes: hh0 lh0 hl0 hh1 lh1 hl1  (ks0 at kb=0, ks1 at kb=32)
        LOAD_A(A0, st, SA_HI, 0);          // aHi ks0
        LOAD_B(B0, st, 0, 0);              // bHi ks0
        LOAD_A(A1, st, SA_LO, 0);          // aLo ks0   (for lh0)
        LOAD_B(B1, st, GN * ROWB, 0);      // bLo ks0   (for hl0)

        MMA_PASS(acc, A0, B0);             // hh0
        MMA_PASS(acc, A1, B0);             // lh0  (B0, A1 dead after)

        LOAD_B(B0, st, 0, 32);             // bHi ks1   (for hh1, lh1)
        LOAD_A(A1, st, SA_HI, 32);         // aHi ks1   (for hh1, hl1)
        MMA_PASS(acc, A0, B1);             // hl0  (A0, B1 dead after)

        LOAD_A(A0, st, SA_LO, 32);         // aLo ks1   (for lh1)
        LOAD_B(B1, st, GN * ROWB, 32);     // bLo ks1   (for hl1)
        MMA_PASS(acc, A1, B0);             // hh1

        MMA_PASS(acc, A0, B0);             // lh1
        MMA_PASS(acc, A1, B1);             // hl1

        stOff += STAGE; if (stOff == NSTAGE * STAGE) stOff = 0;
        wrOff += STAGE; if (wrOff == NSTAGE * STAGE) wrOff = 0;
    }

    // epilogue: + bias, store fp32
    #pragma unroll
    for (int mt = 0; mt < 4; mt++) {
        const int r0 = blockRow + warpM * 64 + mt * 16 + (l >> 2);
        #pragma unroll
        for (int nt = 0; nt < 8; nt++) {
            const int col = blockCol + warpN * 64 + nt * 8 + (l & 3) * 2;
            const float b0 = bias[col], b1 = bias[col + 1];
            float2 v0 = make_float2(acc[mt][nt][0] + b0, acc[mt][nt][1] + b1);
            float2 v1 = make_float2(acc[mt][nt][2] + b0, acc[mt][nt][3] + b1);
            *(float2*)(g_Z + (size_t)r0 * D_EMB + col)       = v0;
            *(float2*)(g_Z + (size_t)(r0 + 8) * D_EMB + col) = v1;
        }
    }
}

// =====================================================================
// Kernel E: prototypes (lower median + mean) with inline stable order
// scan (warp 0 ballot compaction), class stats. One block per class.
// =====================================================================
__global__ __launch_bounds__(256)
void proto_kernel(const int* __restrict__ labels)
{
    const int c   = blockIdx.x;
    const int tid = threadIdx.x;
    const int l   = tid & 31;
    __shared__ float s_sum[256], s_sum2[256];
    __shared__ int   s_idx[K_SHOT];

    if (c < N_WAY && tid < 32) {
        int base = 0;
        for (int i0 = 0; i0 < N_SUPPORT; i0 += 32) {
            const int i = i0 + l;
            const bool match = (i < N_SUPPORT) && (labels[i] == c);
            const unsigned m = __ballot_sync(0xFFFFFFFFu, match);
            if (match) {
                const int pos = base + __popc(m & ((1u << l) - 1u));
                if (pos < K_SHOT) s_idx[pos] = i;
            }
            base += __popc(m);
        }
    }
    __syncthreads();

    float psum = 0.f, psum2 = 0.f;
    if (c < N_WAY) {
        int idx[K_SHOT];
        #pragma unroll
        for (int j = 0; j < K_SHOT; j++) idx[j] = s_idx[j];

        for (int d = tid; d < D_EMB; d += 256) {
            float v[K_SHOT];
            #pragma unroll
            for (int j = 0; j < K_SHOT; j++)
                v[j] = g_Z[(size_t)(N_QUERY + idx[j]) * D_EMB + d];

            float mean = 0.f;
            #pragma unroll
            for (int j = 0; j < K_SHOT; j++) mean += v[j];
            mean *= (1.0f / K_SHOT);

            #pragma unroll
            for (int p = 0; p < K_SHOT - 1; p++)
                #pragma unroll
                for (int q = 0; q < K_SHOT - 1 - p; q++) {
                    float lo = fminf(v[q], v[q + 1]);
                    float hi = fmaxf(v[q], v[q + 1]);
                    v[q] = lo; v[q + 1] = hi;
                }
            const float med = v[(K_SHOT - 1) / 2];
            const float zt  = 0.5f * (med + mean);
            g_proto[(size_t)c * D_EMB + d] = zt;
            psum += zt; psum2 += zt * zt;
        }
    } else {
        for (int d = tid; d < D_EMB; d += 256)
            g_proto[(size_t)c * D_EMB + d] = 0.f;
    }

    s_sum[tid] = psum; s_sum2[tid] = psum2;
    __syncthreads();
    for (int s = 128; s > 0; s >>= 1) {
        if (tid < s) { s_sum[tid] += s_sum[tid + s]; s_sum2[tid] += s_sum2[tid + s]; }
        __syncthreads();
    }
    if (tid == 0 && c < N_WAY) { g_ps[c] = s_sum[0]; g_p2[c] = s_sum2[0]; }
}

// =====================================================================
// Kernel F: per-query-row sum / sum-of-squares — warp per row (fp32)
// =====================================================================
__global__ __launch_bounds__(256)
void qstats_kernel()
{
    const int warp = (blockIdx.x * blockDim.x + threadIdx.x) >> 5;
    const int l    = threadIdx.x & 31;
    if (warp >= N_QUERY) return;
    const float* z = g_Z + (size_t)warp * D_EMB;
    float s = 0.f, s2 = 0.f;
    #pragma unroll
    for (int i = 0; i < 8; i++) {
        float4 v = *(const float4*)(z + (l + i * 32) * 4);
        s  += v.x + v.y + v.z + v.w;
        s2 += v.x * v.x + v.y * v.y + v.z * v.z + v.w * v.w;
    }
    #pragma unroll
    for (int off = 16; off > 0; off >>= 1) {
        s  += __shfl_xor_sync(0xFFFFFFFFu, s,  off);
        s2 += __shfl_xor_sync(0xFFFFFFFFu, s2, off);
    }
    if (l == 0) { g_qs[warp] = s; g_q2[warp] = s2; }
}

// =====================================================================
// Kernel G: distance matrix (SIMT) with fused PairwiseDistance-eps
// =====================================================================
#define DBM 64
#define DBN 128
#define DBK 16
#define DTM 4
#define DTN 8

__global__ __launch_bounds__(256)
void dist_kernel(float* __restrict__ out)
{
    __shared__ float As2[DBK][DBM];
    __shared__ float Bs2[DBK][DBN];

    const int tid      = threadIdx.x;
    const int blockRow = blockIdx.x * DBM;

    const int aRow = tid >> 2;
    const int aCol = (tid & 3) << 2;
    const int tr = (tid >> 4) * DTM;
    const int tc = (tid & 15) * DTN;

    float acc[DTM][DTN] = {};

    const int nk = D_EMB / DBK;
    for (int kt = 0; kt < nk; kt++) {
        const int kc = kt * DBK;
        {
            float4 a = *(const float4*)(g_Z + (size_t)(blockRow + aRow) * D_EMB + kc + aCol);
            As2[aCol + 0][aRow] = a.x; As2[aCol + 1][aRow] = a.y;
            As2[aCol + 2][aRow] = a.z; As2[aCol + 3][aRow] = a.w;
        }
        #pragma unroll
        for (int s = 0; s < 2; s++) {
            const int idx = tid + s * 256;
            const int n   = idx >> 2;
            const int k4  = (idx & 3) << 2;
            float4 p = *(const float4*)(g_proto + (size_t)n * D_EMB + kc + k4);
            Bs2[k4 + 0][n] = p.x; Bs2[k4 + 1][n] = p.y;
            Bs2[k4 + 2][n] = p.z; Bs2[k4 + 3][n] = p.w;
        }
        __syncthreads();

        #pragma unroll
        for (int k = 0; k < DBK; k++) {
            float ar[DTM], br[DTN];
            *(float4*)&ar[0] = *(const float4*)&As2[k][tr];
            *(float4*)&br[0] = *(const float4*)&Bs2[k][tc];
            *(float4*)&br[4] = *(const float4*)&Bs2[k][tc + 4];
            #pragma unroll
            for (int i = 0; i < DTM; i++)
                #pragma unroll
                for (int j = 0; j < DTN; j++)
                    acc[i][j] += ar[i] * br[j];
        }
        __syncthreads();
    }

    const float deps2 = (float)D_EMB * EPS_F * EPS_F;
    #pragma unroll
    for (int i = 0; i < DTM; i++) {
        const int r = blockRow + tr + i;
        const float q2v = g_q2[r];
        const float qsv = g_qs[r];
        #pragma unroll
        for (int j = 0; j < DTN; j++) {
            const int c = tc + j;
            if (c < N_WAY) {
                float sq = q2v + g_p2[c] - 2.0f * acc[i][j]
                         + 2.0f * EPS_F * (qsv - g_ps[c]) + deps2;
                out[(size_t)r * N_WAY + c] = -sqrtf(fmaxf(sq, 0.0f));
            }
        }
    }
}

// =====================================================================
// launch
// =====================================================================
extern "C" void kernel_launch(void* const* d_in, const int* in_sizes, int n_in,
                              void* d_out, int out_size)
{
    const float* support = (const float*)d_in[0];
    const int*   labels  = (const int*)  d_in[1];
    const float* query   = (const float*)d_in[2];
    const float* W       = (const float*)d_in[3];
    const float* b       = (const float*)d_in[4];
    float*       out     = (float*)d_out;

    cudaFuncSetAttribute(gemm_bf16x3,
                         cudaFuncAttributeMaxDynamicSharedMemorySize, GEMM_SMEM);

    {
        const size_t total = (size_t)M_TOT * F_IN / 4;
        convert_A<<<(unsigned)((total + 255) / 256), 256>>>(query, support);
    }
    convert_W<<<dim3(F_IN / 32, D_EMB / 32), dim3(32, 8)>>>(W);

    gemm_bf16x3<<<dim3(D_EMB / GN, M_TOT / GM), 256, GEMM_SMEM>>>(b);

    proto_kernel<<<128, 256>>>(labels);
    qstats_kernel<<<N_QUERY / 8, 256>>>();
    dist_kernel<<<N_QUERY / DBM, 256>>>(out);
}

// round 11
// speedup vs baseline: 1.3181x; 1.3181x over previous
#include <cuda_runtime.h>
#include <cuda_fp16.h>
#include <math.h>
#include <stdint.h>

#define N_WAY     100
#define K_SHOT    10
#define N_SUPPORT 1000
#define N_QUERY   8192
#define F_IN      4096
#define D_EMB     1024
#define EPS_F     1e-6f

#define M_TOT     9216   // 8192 query rows + 1000 support + 24 pad

// ---------------- scratch (static device globals; no allocations) ----------
__device__ __half g_Ahi[(size_t)M_TOT * F_IN];      // fp16 hi of inputs
__device__ __half g_Alo[(size_t)M_TOT * F_IN];      // fp16 lo (exact residual)
__device__ __half g_Wt[(size_t)D_EMB * F_IN];       // W transposed, single fp16
__device__ float g_Z[(size_t)M_TOT * D_EMB];
__device__ float g_proto[128 * D_EMB];
__device__ float g_p2[128];
__device__ float g_ps[128];
__device__ float g_q2[N_QUERY];
__device__ float g_qs[N_QUERY];

// ======================= portable PTX helpers ==============================
__device__ __forceinline__ uint32_t smem_u32(const void* p) {
    uint32_t a;
    asm("{ .reg .u64 t; cvta.to.shared.u64 t, %1; cvt.u32.u64 %0, t; }"
        : "=r"(a) : "l"(p));
    return a;
}
__device__ __forceinline__ void cp_async16(uint32_t dst, const void* src) {
    asm volatile("cp.async.cg.shared.global [%0], [%1], 16;"
                 :: "r"(dst), "l"(src) : "memory");
}
__device__ __forceinline__ void cp_commit() {
    asm volatile("cp.async.commit_group;" ::: "memory");
}
__device__ __forceinline__ void cp_wait1() {
    asm volatile("cp.async.wait_group 1;" ::: "memory");
}
__device__ __forceinline__ void cp_wait0() {
    asm volatile("cp.async.wait_group 0;" ::: "memory");
}
__device__ __forceinline__ void ldmx4(uint32_t* r, uint32_t addr) {
    asm volatile("ldmatrix.sync.aligned.m8n8.x4.shared.b16 {%0,%1,%2,%3}, [%4];"
                 : "=r"(r[0]), "=r"(r[1]), "=r"(r[2]), "=r"(r[3]) : "r"(addr));
}
__device__ __forceinline__ void mma_f16(float* c, const uint32_t* a, const uint32_t* b) {
    asm volatile(
        "mma.sync.aligned.m16n8k16.row.col.f32.f16.f16.f32 "
        "{%0,%1,%2,%3}, {%4,%5,%6,%7}, {%8,%9}, {%0,%1,%2,%3};"
        : "+f"(c[0]), "+f"(c[1]), "+f"(c[2]), "+f"(c[3])
        : "r"(a[0]), "r"(a[1]), "r"(a[2]), "r"(a[3]), "r"(b[0]), "r"(b[1]));
}

// =====================================================================
// Kernel A: split fp32 inputs into fp16 hi + exact fp16 residual
// =====================================================================
__global__ void convert_A(const float* __restrict__ q, const float* __restrict__ s)
{
    size_t i = (size_t)blockIdx.x * blockDim.x + threadIdx.x;
    const size_t total = (size_t)M_TOT * F_IN / 4;
    if (i >= total) return;
    const size_t row = i / (F_IN / 4);
    const size_t seg = i % (F_IN / 4);
    float4 v;
    if (row < N_QUERY)                  v = *(const float4*)(q + row * F_IN + seg * 4);
    else if (row < N_QUERY + N_SUPPORT) v = *(const float4*)(s + (row - N_QUERY) * F_IN + seg * 4);
    else                                v = make_float4(0.f, 0.f, 0.f, 0.f);

    float x[4] = {v.x, v.y, v.z, v.w};
    union H4 { __half h[4]; uint2 u; } uh, ul;
    #pragma unroll
    for (int j = 0; j < 4; j++) {
        __half h = __float2half_rn(x[j]);
        uh.h[j] = h;
        ul.h[j] = __float2half_rn(x[j] - __half2float(h));
    }
    *(uint2*)(g_Ahi + i * 4) = uh.u;
    *(uint2*)(g_Alo + i * 4) = ul.u;
}

// =====================================================================
// Kernel B: transpose W [4096,1024] -> Wt [1024,4096] fp16 single
// =====================================================================
__global__ void convert_W(const float* __restrict__ W)
{
    __shared__ __half th[32][33];
    const int k0 = blockIdx.x * 32, n0 = blockIdx.y * 32;
    const int tx = threadIdx.x, ty = threadIdx.y;   // (32, 8)
    #pragma unroll
    for (int i = 0; i < 4; i++) {
        const int kk = ty + i * 8;
        th[kk][tx] = __float2half_rn(W[(size_t)(k0 + kk) * D_EMB + n0 + tx]);
    }
    __syncthreads();
    #pragma unroll
    for (int i = 0; i < 4; i++) {
        const int nn = ty + i * 8;
        g_Wt[(size_t)(n0 + nn) * F_IN + k0 + tx] = th[tx][nn];
    }
}

// =====================================================================
// Kernel C: fp16x2 tensor-core GEMM (2 passes: ahi*w + alo*w).
// 128x256 tile, 8 warps (64x64), GK=32, 3-stage cp.async,
// compiler-scheduled mainloop (the known-fastest shape).
// =====================================================================
#define GM 128
#define GN 256
#define GK 32
#define NCH (F_IN / GK)          // 128
#define ROWB 80                  // 32 fp16 (64B) + 16B pad
#define SA_HI 0
#define SA_LO (GM * ROWB)                      // 10240
#define SB    (2 * GM * ROWB)                  // 20480
#define STAGE (2 * GM * ROWB + GN * ROWB)      // 40960
#define NSTAGE 3
#define GEMM_SMEM (NSTAGE * STAGE)             // 122880

__device__ __forceinline__ void copy_chunk(uint32_t sb, int blockRow, int blockCol,
                                           int c, int tid)
{
    const size_t kc = (size_t)c * GK;
    // A hi+lo: 128 rows x 4 segs x 2 arrays = 1024 x 16B, 256 thr -> 4 iters
    #pragma unroll
    for (int i = 0; i < 4; i++) {
        const int id  = tid + i * 256;
        const int arr = id >> 9;            // 0 hi, 1 lo
        const int rid = (id >> 2) & 127;
        const int seg = id & 3;
        const char* src = (const char*)(arr ? g_Alo : g_Ahi)
                        + ((size_t)(blockRow + rid) * F_IN + kc) * 2 + seg * 16;
        cp_async16(sb + arr * (GM * ROWB) + rid * ROWB + seg * 16, src);
    }
    // B: 256 rows x 4 segs = 1024 x 16B -> 4 iters
    #pragma unroll
    for (int i = 0; i < 4; i++) {
        const int id  = tid + i * 256;
        const int rid = id >> 2;
        const int seg = id & 3;
        const char* src = (const char*)g_Wt
                        + ((size_t)(blockCol + rid) * F_IN + kc) * 2 + seg * 16;
        cp_async16(sb + SB + rid * ROWB + seg * 16, src);
    }
}

// one full pass over the 64x64 warp tile: 32 HMMA
#define MMA_PASS(ACC, A, B)                                   \
    _Pragma("unroll")                                         \
    for (int mt = 0; mt < 4; mt++) {                          \
        _Pragma("unroll")                                     \
        for (int p = 0; p < 4; p++) {                         \
            mma_f16(ACC[mt][p * 2 + 0], A[mt], &B[p][0]);     \
            mma_f16(ACC[mt][p * 2 + 1], A[mt], &B[p][2]);     \
        }                                                     \
    }

__global__ __launch_bounds__(256, 1)
void gemm_fp16x2(const float* __restrict__ bias)
{
    extern __shared__ char smem[];
    const uint32_t sbase = smem_u32(smem);
    const int tid = threadIdx.x;
    const int wid = tid >> 5;
    const int l   = tid & 31;
    const int warpM = wid >> 2;          // 0..1 -> 64-row strip
    const int warpN = wid & 3;           // 0..3 -> 64-col strip
    const int blockRow = blockIdx.y * GM;
    const int blockCol = blockIdx.x * GN;

    const uint32_t aOff = (uint32_t)((warpM * 64 + (l & 15)) * ROWB + (l >> 4) * 16);
    uint32_t bOff[4];
    #pragma unroll
    for (int p = 0; p < 4; p++)
        bOff[p] = (uint32_t)(SB + (warpN * 64 + p * 16 + ((l >> 4) & 1) * 8 + (l & 7)) * ROWB
                             + ((l >> 3) & 1) * 16);

    float acc[4][8][4];
    #pragma unroll
    for (int mt = 0; mt < 4; mt++)
        #pragma unroll
        for (int nt = 0; nt < 8; nt++)
            #pragma unroll
            for (int r = 0; r < 4; r++) acc[mt][nt][r] = 0.f;

    copy_chunk(sbase, blockRow, blockCol, 0, tid);
    cp_commit();
    copy_chunk(sbase + STAGE, blockRow, blockCol, 1, tid);
    cp_commit();

    uint32_t stOff = 0;
    uint32_t wrOff = 2 * STAGE;

    for (int c = 0; c < NCH; c++) {
        cp_wait1();
        __syncthreads();

        if (c + 2 < NCH) copy_chunk(sbase + wrOff, blockRow, blockCol, c + 2, tid);
        cp_commit();

        const uint32_t st = sbase + stOff;
        #pragma unroll
        for (int ks = 0; ks < 2; ks++) {
            const uint32_t kb = ks * 32;
            uint32_t aH[4][4], aL[4][4], bF[4][4];

            #pragma unroll
            for (int mt = 0; mt < 4; mt++) ldmx4(aH[mt], st + aOff + mt * (16 * ROWB) + kb);
            #pragma unroll
            for (int p = 0; p < 4; p++)   ldmx4(bF[p], st + bOff[p] + kb);

            // pass 1: hi * w
            MMA_PASS(acc, aH, bF);

            // pass 2: lo * w
            #pragma unroll
            for (int mt = 0; mt < 4; mt++) ldmx4(aL[mt], st + aOff + SA_LO + mt * (16 * ROWB) + kb);
            MMA_PASS(acc, aL, bF);
        }

        stOff += STAGE; if (stOff == NSTAGE * STAGE) stOff = 0;
        wrOff += STAGE; if (wrOff == NSTAGE * STAGE) wrOff = 0;
    }

    // epilogue: + bias, store fp32
    #pragma unroll
    for (int mt = 0; mt < 4; mt++) {
        const int r0 = blockRow + warpM * 64 + mt * 16 + (l >> 2);
        #pragma unroll
        for (int nt = 0; nt < 8; nt++) {
            const int col = blockCol + warpN * 64 + nt * 8 + (l & 3) * 2;
            const float b0 = bias[col], b1 = bias[col + 1];
            float2 v0 = make_float2(acc[mt][nt][0] + b0, acc[mt][nt][1] + b1);
            float2 v1 = make_float2(acc[mt][nt][2] + b0, acc[mt][nt][3] + b1);
            *(float2*)(g_Z + (size_t)r0 * D_EMB + col)       = v0;
            *(float2*)(g_Z + (size_t)(r0 + 8) * D_EMB + col) = v1;
        }
    }
}

// =====================================================================
// Kernel E: prototypes (lower median + mean) with inline stable order
// scan (warp 0 ballot compaction), class stats. One block per class.
// =====================================================================
__global__ __launch_bounds__(256)
void proto_kernel(const int* __restrict__ labels)
{
    const int c   = blockIdx.x;
    const int tid = threadIdx.x;
    const int l   = tid & 31;
    __shared__ float s_sum[256], s_sum2[256];
    __shared__ int   s_idx[K_SHOT];

    if (c < N_WAY && tid < 32) {
        int base = 0;
        for (int i0 = 0; i0 < N_SUPPORT; i0 += 32) {
            const int i = i0 + l;
            const bool match = (i < N_SUPPORT) && (labels[i] == c);
            const unsigned m = __ballot_sync(0xFFFFFFFFu, match);
            if (match) {
                const int pos = base + __popc(m & ((1u << l) - 1u));
                if (pos < K_SHOT) s_idx[pos] = i;
            }
            base += __popc(m);
        }
    }
    __syncthreads();

    float psum = 0.f, psum2 = 0.f;
    if (c < N_WAY) {
        int idx[K_SHOT];
        #pragma unroll
        for (int j = 0; j < K_SHOT; j++) idx[j] = s_idx[j];

        for (int d = tid; d < D_EMB; d += 256) {
            float v[K_SHOT];
            #pragma unroll
            for (int j = 0; j < K_SHOT; j++)
                v[j] = g_Z[(size_t)(N_QUERY + idx[j]) * D_EMB + d];

            float mean = 0.f;
            #pragma unroll
            for (int j = 0; j < K_SHOT; j++) mean += v[j];
            mean *= (1.0f / K_SHOT);

            #pragma unroll
            for (int p = 0; p < K_SHOT - 1; p++)
                #pragma unroll
                for (int q = 0; q < K_SHOT - 1 - p; q++) {
                    float lo = fminf(v[q], v[q + 1]);
                    float hi = fmaxf(v[q], v[q + 1]);
                    v[q] = lo; v[q + 1] = hi;
                }
            const float med = v[(K_SHOT - 1) / 2];
            const float zt  = 0.5f * (med + mean);
            g_proto[(size_t)c * D_EMB + d] = zt;
            psum += zt; psum2 += zt * zt;
        }
    } else {
        for (int d = tid; d < D_EMB; d += 256)
            g_proto[(size_t)c * D_EMB + d] = 0.f;
    }

    s_sum[tid] = psum; s_sum2[tid] = psum2;
    __syncthreads();
    for (int s = 128; s > 0; s >>= 1) {
        if (tid < s) { s_sum[tid] += s_sum[tid + s]; s_sum2[tid] += s_sum2[tid + s]; }
        __syncthreads();
    }
    if (tid == 0 && c < N_WAY) { g_ps[c] = s_sum[0]; g_p2[c] = s_sum2[0]; }
}

// =====================================================================
// Kernel F: per-query-row sum / sum-of-squares — warp per row (fp32)
// =====================================================================
__global__ __launch_bounds__(256)
void qstats_kernel()
{
    const int warp = (blockIdx.x * blockDim.x + threadIdx.x) >> 5;
    const int l    = threadIdx.x & 31;
    if (warp >= N_QUERY) return;
    const float* z = g_Z + (size_t)warp * D_EMB;
    float s = 0.f, s2 = 0.f;
    #pragma unroll
    for (int i = 0; i < 8; i++) {
        float4 v = *(const float4*)(z + (l + i * 32) * 4);
        s  += v.x + v.y + v.z + v.w;
        s2 += v.x * v.x + v.y * v.y + v.z * v.z + v.w * v.w;
    }
    #pragma unroll
    for (int off = 16; off > 0; off >>= 1) {
        s  += __shfl_xor_sync(0xFFFFFFFFu, s,  off);
        s2 += __shfl_xor_sync(0xFFFFFFFFu, s2, off);
    }
    if (l == 0) { g_qs[warp] = s; g_q2[warp] = s2; }
}

// =====================================================================
// Kernel G: distance matrix (SIMT) with fused PairwiseDistance-eps
// =====================================================================
#define DBM 64
#define DBN 128
#define DBK 16
#define DTM 4
#define DTN 8

__global__ __launch_bounds__(256)
void dist_kernel(float* __restrict__ out)
{
    __shared__ float As2[DBK][DBM];
    __shared__ float Bs2[DBK][DBN];

    const int tid      = threadIdx.x;
    const int blockRow = blockIdx.x * DBM;

    const int aRow = tid >> 2;
    const int aCol = (tid & 3) << 2;
    const int tr = (tid >> 4) * DTM;
    const int tc = (tid & 15) * DTN;

    float acc[DTM][DTN] = {};

    const int nk = D_EMB / DBK;
    for (int kt = 0; kt < nk; kt++) {
        const int kc = kt * DBK;
        {
            float4 a = *(const float4*)(g_Z + (size_t)(blockRow + aRow) * D_EMB + kc + aCol);
            As2[aCol + 0][aRow] = a.x; As2[aCol + 1][aRow] = a.y;
            As2[aCol + 2][aRow] = a.z; As2[aCol + 3][aRow] = a.w;
        }
        #pragma unroll
        for (int s = 0; s < 2; s++) {
            const int idx = tid + s * 256;
            const int n   = idx >> 2;
            const int k4  = (idx & 3) << 2;
            float4 p = *(const float4*)(g_proto + (size_t)n * D_EMB + kc + k4);
            Bs2[k4 + 0][n] = p.x; Bs2[k4 + 1][n] = p.y;
            Bs2[k4 + 2][n] = p.z; Bs2[k4 + 3][n] = p.w;
        }
        __syncthreads();

        #pragma unroll
        for (int k = 0; k < DBK; k++) {
            float ar[DTM], br[DTN];
            *(float4*)&ar[0] = *(const float4*)&As2[k][tr];
            *(float4*)&br[0] = *(const float4*)&Bs2[k][tc];
            *(float4*)&br[4] = *(const float4*)&Bs2[k][tc + 4];
            #pragma unroll
            for (int i = 0; i < DTM; i++)
                #pragma unroll
                for (int j = 0; j < DTN; j++)
                    acc[i][j] += ar[i] * br[j];
        }
        __syncthreads();
    }

    const float deps2 = (float)D_EMB * EPS_F * EPS_F;
    #pragma unroll
    for (int i = 0; i < DTM; i++) {
        const int r = blockRow + tr + i;
        const float q2v = g_q2[r];
        const float qsv = g_qs[r];
        #pragma unroll
        for (int j = 0; j < DTN; j++) {
            const int c = tc + j;
            if (c < N_WAY) {
                float sq = q2v + g_p2[c] - 2.0f * acc[i][j]
                         + 2.0f * EPS_F * (qsv - g_ps[c]) + deps2;
                out[(size_t)r * N_WAY + c] = -sqrtf(fmaxf(sq, 0.0f));
            }
        }
    }
}

// =====================================================================
// launch
// =====================================================================
extern "C" void kernel_launch(void* const* d_in, const int* in_sizes, int n_in,
                              void* d_out, int out_size)
{
    const float* support = (const float*)d_in[0];
    const int*   labels  = (const int*)  d_in[1];
    const float* query   = (const float*)d_in[2];
    const float* W       = (const float*)d_in[3];
    const float* b       = (const float*)d_in[4];
    float*       out     = (float*)d_out;

    cudaFuncSetAttribute(gemm_fp16x2,
                         cudaFuncAttributeMaxDynamicSharedMemorySize, GEMM_SMEM);

    {
        const size_t total = (size_t)M_TOT * F_IN / 4;
        convert_A<<<(unsigned)((total + 255) / 256), 256>>>(query, support);
    }
    convert_W<<<dim3(F_IN / 32, D_EMB / 32), dim3(32, 8)>>>(W);

    gemm_fp16x2<<<dim3(D_EMB / GN, M_TOT / GM), 256, GEMM_SMEM>>>(b);

    proto_kernel<<<128, 256>>>(labels);
    qstats_kernel<<<N_QUERY / 8, 256>>>();
    dist_kernel<<<N_QUERY / DBM, 256>>>(out);
}

// round 12
// speedup vs baseline: 1.8261x; 1.3854x over previous
#include <cuda_runtime.h>
#include <cuda_fp16.h>
#include <math.h>
#include <stdint.h>

#define N_WAY     100
#define K_SHOT    10
#define N_SUPPORT 1000
#define N_QUERY   8192
#define F_IN      4096
#define D_EMB     1024
#define EPS_F     1e-6f

#define M_TOT     9216   // 8192 query rows + 1000 support + 24 pad

// ---------------- scratch (static device globals; no allocations) ----------
__device__ __half g_A[(size_t)M_TOT * F_IN];        // fp16 inputs
__device__ __half g_Wt[(size_t)D_EMB * F_IN];       // W transposed, fp16
__device__ float g_Z[(size_t)M_TOT * D_EMB];
__device__ float g_proto[128 * D_EMB];
__device__ float g_p2[128];
__device__ float g_ps[128];
__device__ float g_q2[N_QUERY];
__device__ float g_qs[N_QUERY];

// ======================= portable PTX helpers ==============================
__device__ __forceinline__ uint32_t smem_u32(const void* p) {
    uint32_t a;
    asm("{ .reg .u64 t; cvta.to.shared.u64 t, %1; cvt.u32.u64 %0, t; }"
        : "=r"(a) : "l"(p));
    return a;
}
__device__ __forceinline__ void cp_async16(uint32_t dst, const void* src) {
    asm volatile("cp.async.cg.shared.global [%0], [%1], 16;"
                 :: "r"(dst), "l"(src) : "memory");
}
__device__ __forceinline__ void cp_commit() {
    asm volatile("cp.async.commit_group;" ::: "memory");
}
__device__ __forceinline__ void cp_wait1() {
    asm volatile("cp.async.wait_group 1;" ::: "memory");
}
__device__ __forceinline__ void ldmx4(uint32_t* r, uint32_t addr) {
    asm volatile("ldmatrix.sync.aligned.m8n8.x4.shared.b16 {%0,%1,%2,%3}, [%4];"
                 : "=r"(r[0]), "=r"(r[1]), "=r"(r[2]), "=r"(r[3]) : "r"(addr));
}
__device__ __forceinline__ void mma_f16(float* c, const uint32_t* a, const uint32_t* b) {
    asm volatile(
        "mma.sync.aligned.m16n8k16.row.col.f32.f16.f16.f32 "
        "{%0,%1,%2,%3}, {%4,%5,%6,%7}, {%8,%9}, {%0,%1,%2,%3};"
        : "+f"(c[0]), "+f"(c[1]), "+f"(c[2]), "+f"(c[3])
        : "r"(a[0]), "r"(a[1]), "r"(a[2]), "r"(a[3]), "r"(b[0]), "r"(b[1]));
}

// =====================================================================
// Kernel A: convert fp32 inputs to fp16
// =====================================================================
__global__ void convert_A(const float* __restrict__ q, const float* __restrict__ s)
{
    size_t i = (size_t)blockIdx.x * blockDim.x + threadIdx.x;
    const size_t total = (size_t)M_TOT * F_IN / 4;
    if (i >= total) return;
    const size_t row = i / (F_IN / 4);
    const size_t seg = i % (F_IN / 4);
    float4 v;
    if (row < N_QUERY)                  v = *(const float4*)(q + row * F_IN + seg * 4);
    else if (row < N_QUERY + N_SUPPORT) v = *(const float4*)(s + (row - N_QUERY) * F_IN + seg * 4);
    else                                v = make_float4(0.f, 0.f, 0.f, 0.f);

    union H4 { __half h[4]; uint2 u; } uh;
    uh.h[0] = __float2half_rn(v.x);
    uh.h[1] = __float2half_rn(v.y);
    uh.h[2] = __float2half_rn(v.z);
    uh.h[3] = __float2half_rn(v.w);
    *(uint2*)(g_A + i * 4) = uh.u;
}

// =====================================================================
// Kernel B: transpose W [4096,1024] -> Wt [1024,4096] fp16
// =====================================================================
__global__ void convert_W(const float* __restrict__ W)
{
    __shared__ __half th[32][33];
    const int k0 = blockIdx.x * 32, n0 = blockIdx.y * 32;
    const int tx = threadIdx.x, ty = threadIdx.y;   // (32, 8)
    #pragma unroll
    for (int i = 0; i < 4; i++) {
        const int kk = ty + i * 8;
        th[kk][tx] = __float2half_rn(W[(size_t)(k0 + kk) * D_EMB + n0 + tx]);
    }
    __syncthreads();
    #pragma unroll
    for (int i = 0; i < 4; i++) {
        const int nn = ty + i * 8;
        g_Wt[(size_t)(n0 + nn) * F_IN + k0 + tx] = th[tx][nn];
    }
}

// =====================================================================
// Kernel C: single-pass fp16 tensor-core GEMM.
// 128x256 tile, 8 warps (64x64), GK=32, 3-stage cp.async,
// compiler-scheduled mainloop (the proven-fastest shape).
// =====================================================================
#define GM 128
#define GN 256
#define GK 32
#define NCH (F_IN / GK)          // 128
#define ROWB 80                  // 32 fp16 (64B) + 16B pad
#define SA    0
#define SB    (GM * ROWB)                      // 10240
#define STAGE (GM * ROWB + GN * ROWB)          // 30720
#define NSTAGE 3
#define GEMM_SMEM (NSTAGE * STAGE)             // 92160

__device__ __forceinline__ void copy_chunk(uint32_t sb, int blockRow, int blockCol,
                                           int c, int tid)
{
    const size_t kc = (size_t)c * GK;
    // A: 128 rows x 4 segs = 512 x 16B, 256 thr -> 2 iters
    #pragma unroll
    for (int i = 0; i < 2; i++) {
        const int id  = tid + i * 256;
        const int rid = id >> 2;
        const int seg = id & 3;
        const char* src = (const char*)g_A
                        + ((size_t)(blockRow + rid) * F_IN + kc) * 2 + seg * 16;
        cp_async16(sb + SA + rid * ROWB + seg * 16, src);
    }
    // B: 256 rows x 4 segs = 1024 x 16B -> 4 iters
    #pragma unroll
    for (int i = 0; i < 4; i++) {
        const int id  = tid + i * 256;
        const int rid = id >> 2;
        const int seg = id & 3;
        const char* src = (const char*)g_Wt
                        + ((size_t)(blockCol + rid) * F_IN + kc) * 2 + seg * 16;
        cp_async16(sb + SB + rid * ROWB + seg * 16, src);
    }
}

// one full pass over the 64x64 warp tile: 32 HMMA
#define MMA_PASS(ACC, A, B)                                   \
    _Pragma("unroll")                                         \
    for (int mt = 0; mt < 4; mt++) {                          \
        _Pragma("unroll")                                     \
        for (int p = 0; p < 4; p++) {                         \
            mma_f16(ACC[mt][p * 2 + 0], A[mt], &B[p][0]);     \
            mma_f16(ACC[mt][p * 2 + 1], A[mt], &B[p][2]);     \
        }                                                     \
    }

__global__ __launch_bounds__(256, 1)
void gemm_fp16(const float* __restrict__ bias)
{
    extern __shared__ char smem[];
    const uint32_t sbase = smem_u32(smem);
    const int tid = threadIdx.x;
    const int wid = tid >> 5;
    const int l   = tid & 31;
    const int warpM = wid >> 2;          // 0..1 -> 64-row strip
    const int warpN = wid & 3;           // 0..3 -> 64-col strip
    const int blockRow = blockIdx.y * GM;
    const int blockCol = blockIdx.x * GN;

    const uint32_t aOff = (uint32_t)((warpM * 64 + (l & 15)) * ROWB + (l >> 4) * 16);
    uint32_t bOff[4];
    #pragma unroll
    for (int p = 0; p < 4; p++)
        bOff[p] = (uint32_t)(SB + (warpN * 64 + p * 16 + ((l >> 4) & 1) * 8 + (l & 7)) * ROWB
                             + ((l >> 3) & 1) * 16);

    float acc[4][8][4];
    #pragma unroll
    for (int mt = 0; mt < 4; mt++)
        #pragma unroll
        for (int nt = 0; nt < 8; nt++)
            #pragma unroll
            for (int r = 0; r < 4; r++) acc[mt][nt][r] = 0.f;

    copy_chunk(sbase, blockRow, blockCol, 0, tid);
    cp_commit();
    copy_chunk(sbase + STAGE, blockRow, blockCol, 1, tid);
    cp_commit();

    uint32_t stOff = 0;
    uint32_t wrOff = 2 * STAGE;

    for (int c = 0; c < NCH; c++) {
        cp_wait1();
        __syncthreads();

        if (c + 2 < NCH) copy_chunk(sbase + wrOff, blockRow, blockCol, c + 2, tid);
        cp_commit();

        const uint32_t st = sbase + stOff;
        #pragma unroll
        for (int ks = 0; ks < 2; ks++) {
            const uint32_t kb = ks * 32;
            uint32_t aF[4][4], bF[4][4];

            #pragma unroll
            for (int mt = 0; mt < 4; mt++) ldmx4(aF[mt], st + aOff + mt * (16 * ROWB) + kb);
            #pragma unroll
            for (int p = 0; p < 4; p++)   ldmx4(bF[p], st + bOff[p] + kb);

            MMA_PASS(acc, aF, bF);
        }

        stOff += STAGE; if (stOff == NSTAGE * STAGE) stOff = 0;
        wrOff += STAGE; if (wrOff == NSTAGE * STAGE) wrOff = 0;
    }

    // epilogue: + bias, store fp32
    #pragma unroll
    for (int mt = 0; mt < 4; mt++) {
        const int r0 = blockRow + warpM * 64 + mt * 16 + (l >> 2);
        #pragma unroll
        for (int nt = 0; nt < 8; nt++) {
            const int col = blockCol + warpN * 64 + nt * 8 + (l & 3) * 2;
            const float b0 = bias[col], b1 = bias[col + 1];
            float2 v0 = make_float2(acc[mt][nt][0] + b0, acc[mt][nt][1] + b1);
            float2 v1 = make_float2(acc[mt][nt][2] + b0, acc[mt][nt][3] + b1);
            *(float2*)(g_Z + (size_t)r0 * D_EMB + col)       = v0;
            *(float2*)(g_Z + (size_t)(r0 + 8) * D_EMB + col) = v1;
        }
    }
}

// =====================================================================
// Kernel E: prototypes (lower median + mean) with inline stable order
// scan (warp 0 ballot compaction), class stats. One block per class.
// =====================================================================
__global__ __launch_bounds__(256)
void proto_kernel(const int* __restrict__ labels)
{
    const int c   = blockIdx.x;
    const int tid = threadIdx.x;
    const int l   = tid & 31;
    __shared__ float s_sum[256], s_sum2[256];
    __shared__ int   s_idx[K_SHOT];

    if (c < N_WAY && tid < 32) {
        int base = 0;
        for (int i0 = 0; i0 < N_SUPPORT; i0 += 32) {
            const int i = i0 + l;
            const bool match = (i < N_SUPPORT) && (labels[i] == c);
            const unsigned m = __ballot_sync(0xFFFFFFFFu, match);
            if (match) {
                const int pos = base + __popc(m & ((1u << l) - 1u));
                if (pos < K_SHOT) s_idx[pos] = i;
            }
            base += __popc(m);
        }
    }
    __syncthreads();

    float psum = 0.f, psum2 = 0.f;
    if (c < N_WAY) {
        int idx[K_SHOT];
        #pragma unroll
        for (int j = 0; j < K_SHOT; j++) idx[j] = s_idx[j];

        for (int d = tid; d < D_EMB; d += 256) {
            float v[K_SHOT];
            #pragma unroll
            for (int j = 0; j < K_SHOT; j++)
                v[j] = g_Z[(size_t)(N_QUERY + idx[j]) * D_EMB + d];

            float mean = 0.f;
            #pragma unroll
            for (int j = 0; j < K_SHOT; j++) mean += v[j];
            mean *= (1.0f / K_SHOT);

            #pragma unroll
            for (int p = 0; p < K_SHOT - 1; p++)
                #pragma unroll
                for (int q = 0; q < K_SHOT - 1 - p; q++) {
                    float lo = fminf(v[q], v[q + 1]);
                    float hi = fmaxf(v[q], v[q + 1]);
                    v[q] = lo; v[q + 1] = hi;
                }
            const float med = v[(K_SHOT - 1) / 2];
            const float zt  = 0.5f * (med + mean);
            g_proto[(size_t)c * D_EMB + d] = zt;
            psum += zt; psum2 += zt * zt;
        }
    } else {
        for (int d = tid; d < D_EMB; d += 256)
            g_proto[(size_t)c * D_EMB + d] = 0.f;
    }

    s_sum[tid] = psum; s_sum2[tid] = psum2;
    __syncthreads();
    for (int s = 128; s > 0; s >>= 1) {
        if (tid < s) { s_sum[tid] += s_sum[tid + s]; s_sum2[tid] += s_sum2[tid + s]; }
        __syncthreads();
    }
    if (tid == 0 && c < N_WAY) { g_ps[c] = s_sum[0]; g_p2[c] = s_sum2[0]; }
}

// =====================================================================
// Kernel F: per-query-row sum / sum-of-squares — warp per row (fp32)
// =====================================================================
__global__ __launch_bounds__(256)
void qstats_kernel()
{
    const int warp = (blockIdx.x * blockDim.x + threadIdx.x) >> 5;
    const int l    = threadIdx.x & 31;
    if (warp >= N_QUERY) return;
    const float* z = g_Z + (size_t)warp * D_EMB;
    float s = 0.f, s2 = 0.f;
    #pragma unroll
    for (int i = 0; i < 8; i++) {
        float4 v = *(const float4*)(z + (l + i * 32) * 4);
        s  += v.x + v.y + v.z + v.w;
        s2 += v.x * v.x + v.y * v.y + v.z * v.z + v.w * v.w;
    }
    #pragma unroll
    for (int off = 16; off > 0; off >>= 1) {
        s  += __shfl_xor_sync(0xFFFFFFFFu, s,  off);
        s2 += __shfl_xor_sync(0xFFFFFFFFu, s2, off);
    }
    if (l == 0) { g_qs[warp] = s; g_q2[warp] = s2; }
}

// =====================================================================
// Kernel G: distance matrix (SIMT) with fused PairwiseDistance-eps
// =====================================================================
#define DBM 64
#define DBN 128
#define DBK 16
#define DTM 4
#define DTN 8

__global__ __launch_bounds__(256)
void dist_kernel(float* __restrict__ out)
{
    __shared__ float As2[DBK][DBM];
    __shared__ float Bs2[DBK][DBN];

    const int tid      = threadIdx.x;
    const int blockRow = blockIdx.x * DBM;

    const int aRow = tid >> 2;
    const int aCol = (tid & 3) << 2;
    const int tr = (tid >> 4) * DTM;
    const int tc = (tid & 15) * DTN;

    float acc[DTM][DTN] = {};

    const int nk = D_EMB / DBK;
    for (int kt = 0; kt < nk; kt++) {
        const int kc = kt * DBK;
        {
            float4 a = *(const float4*)(g_Z + (size_t)(blockRow + aRow) * D_EMB + kc + aCol);
            As2[aCol + 0][aRow] = a.x; As2[aCol + 1][aRow] = a.y;
            As2[aCol + 2][aRow] = a.z; As2[aCol + 3][aRow] = a.w;
        }
        #pragma unroll
        for (int s = 0; s < 2; s++) {
            const int idx = tid + s * 256;
            const int n   = idx >> 2;
            const int k4  = (idx & 3) << 2;
            float4 p = *(const float4*)(g_proto + (size_t)n * D_EMB + kc + k4);
            Bs2[k4 + 0][n] = p.x; Bs2[k4 + 1][n] = p.y;
            Bs2[k4 + 2][n] = p.z; Bs2[k4 + 3][n] = p.w;
        }
        __syncthreads();

        #pragma unroll
        for (int k = 0; k < DBK; k++) {
            float ar[DTM], br[DTN];
            *(float4*)&ar[0] = *(const float4*)&As2[k][tr];
            *(float4*)&br[0] = *(const float4*)&Bs2[k][tc];
            *(float4*)&br[4] = *(const float4*)&Bs2[k][tc + 4];
            #pragma unroll
            for (int i = 0; i < DTM; i++)
                #pragma unroll
                for (int j = 0; j < DTN; j++)
                    acc[i][j] += ar[i] * br[j];
        }
        __syncthreads();
    }

    const float deps2 = (float)D_EMB * EPS_F * EPS_F;
    #pragma unroll
    for (int i = 0; i < DTM; i++) {
        const int r = blockRow + tr + i;
        const float q2v = g_q2[r];
        const float qsv = g_qs[r];
        #pragma unroll
        for (int j = 0; j < DTN; j++) {
            const int c = tc + j;
            if (c < N_WAY) {
                float sq = q2v + g_p2[c] - 2.0f * acc[i][j]
                         + 2.0f * EPS_F * (qsv - g_ps[c]) + deps2;
                out[(size_t)r * N_WAY + c] = -sqrtf(fmaxf(sq, 0.0f));
            }
        }
    }
}

// =====================================================================
// launch
// =====================================================================
extern "C" void kernel_launch(void* const* d_in, const int* in_sizes, int n_in,
                              void* d_out, int out_size)
{
    const float* support = (const float*)d_in[0];
    const int*   labels  = (const int*)  d_in[1];
    const float* query   = (const float*)d_in[2];
    const float* W       = (const float*)d_in[3];
    const float* b       = (const float*)d_in[4];
    float*       out     = (float*)d_out;

    cudaFuncSetAttribute(gemm_fp16,
                         cudaFuncAttributeMaxDynamicSharedMemorySize, GEMM_SMEM);

    {
        const size_t total = (size_t)M_TOT * F_IN / 4;
        convert_A<<<(unsigned)((total + 255) / 256), 256>>>(query, support);
    }
    convert_W<<<dim3(F_IN / 32, D_EMB / 32), dim3(32, 8)>>>(W);

    gemm_fp16<<<dim3(D_EMB / GN, M_TOT / GM), 256, GEMM_SMEM>>>(b);

    proto_kernel<<<128, 256>>>(labels);
    qstats_kernel<<<N_QUERY / 8, 256>>>();
    dist_kernel<<<N_QUERY / DBM, 256>>>(out);
}

// round 13
// speedup vs baseline: 2.6200x; 1.4348x over previous
#include <cuda_runtime.h>
#include <cuda_fp16.h>
#include <math.h>
#include <stdint.h>

#define N_WAY     100
#define K_SHOT    10
#define N_SUPPORT 1000
#define N_QUERY   8192
#define F_IN      4096
#define D_EMB     1024
#define EPS_F     1e-6f

#define M_TOT     9216   // 8192 query rows + 1000 support + 24 pad

// ---------------- scratch (static device globals; no allocations) ----------
__device__ __half g_A[(size_t)M_TOT * F_IN];        // fp16 inputs
__device__ __half g_Wt[(size_t)D_EMB * F_IN];       // W transposed, fp16
__device__ float  g_Z[(size_t)M_TOT * D_EMB];       // fp32 embeddings (all rows)
__device__ __half g_Zh[(size_t)N_QUERY * D_EMB];    // fp16 query embeddings
__device__ __half g_Ph[128 * D_EMB];                // fp16 prototypes (pad 128)
__device__ float g_p2[128];
__device__ float g_ps[128];
__device__ float g_q2[N_QUERY];
__device__ float g_qs[N_QUERY];

// ======================= portable PTX helpers ==============================
__device__ __forceinline__ uint32_t smem_u32(const void* p) {
    uint32_t a;
    asm("{ .reg .u64 t; cvta.to.shared.u64 t, %1; cvt.u32.u64 %0, t; }"
        : "=r"(a) : "l"(p));
    return a;
}
__device__ __forceinline__ void cp_async16(uint32_t dst, const void* src) {
    asm volatile("cp.async.cg.shared.global [%0], [%1], 16;"
                 :: "r"(dst), "l"(src) : "memory");
}
__device__ __forceinline__ void cp_commit() {
    asm volatile("cp.async.commit_group;" ::: "memory");
}
__device__ __forceinline__ void cp_wait1() {
    asm volatile("cp.async.wait_group 1;" ::: "memory");
}
__device__ __forceinline__ void cp_wait0() {
    asm volatile("cp.async.wait_group 0;" ::: "memory");
}
__device__ __forceinline__ void ldmx4(uint32_t* r, uint32_t addr) {
    asm volatile("ldmatrix.sync.aligned.m8n8.x4.shared.b16 {%0,%1,%2,%3}, [%4];"
                 : "=r"(r[0]), "=r"(r[1]), "=r"(r[2]), "=r"(r[3]) : "r"(addr));
}
__device__ __forceinline__ void mma_f16(float* c, const uint32_t* a, const uint32_t* b) {
    asm volatile(
        "mma.sync.aligned.m16n8k16.row.col.f32.f16.f16.f32 "
        "{%0,%1,%2,%3}, {%4,%5,%6,%7}, {%8,%9}, {%0,%1,%2,%3};"
        : "+f"(c[0]), "+f"(c[1]), "+f"(c[2]), "+f"(c[3])
        : "r"(a[0]), "r"(a[1]), "r"(a[2]), "r"(a[3]), "r"(b[0]), "r"(b[1]));
}

// =====================================================================
// Kernel A: convert fp32 inputs to fp16
// =====================================================================
__global__ void convert_A(const float* __restrict__ q, const float* __restrict__ s)
{
    size_t i = (size_t)blockIdx.x * blockDim.x + threadIdx.x;
    const size_t total = (size_t)M_TOT * F_IN / 4;
    if (i >= total) return;
    const size_t row = i / (F_IN / 4);
    const size_t seg = i % (F_IN / 4);
    float4 v;
    if (row < N_QUERY)                  v = *(const float4*)(q + row * F_IN + seg * 4);
    else if (row < N_QUERY + N_SUPPORT) v = *(const float4*)(s + (row - N_QUERY) * F_IN + seg * 4);
    else                                v = make_float4(0.f, 0.f, 0.f, 0.f);

    union H4 { __half h[4]; uint2 u; } uh;
    uh.h[0] = __float2half_rn(v.x);
    uh.h[1] = __float2half_rn(v.y);
    uh.h[2] = __float2half_rn(v.z);
    uh.h[3] = __float2half_rn(v.w);
    *(uint2*)(g_A + i * 4) = uh.u;
}

// =====================================================================
// Kernel B: transpose W [4096,1024] -> Wt [1024,4096] fp16
// =====================================================================
__global__ void convert_W(const float* __restrict__ W)
{
    __shared__ __half th[32][33];
    const int k0 = blockIdx.x * 32, n0 = blockIdx.y * 32;
    const int tx = threadIdx.x, ty = threadIdx.y;   // (32, 8)
    #pragma unroll
    for (int i = 0; i < 4; i++) {
        const int kk = ty + i * 8;
        th[kk][tx] = __float2half_rn(W[(size_t)(k0 + kk) * D_EMB + n0 + tx]);
    }
    __syncthreads();
    #pragma unroll
    for (int i = 0; i < 4; i++) {
        const int nn = ty + i * 8;
        g_Wt[(size_t)(n0 + nn) * F_IN + k0 + tx] = th[tx][nn];
    }
}

// =====================================================================
// Kernel C: single-pass fp16 GEMM, 128x256 tile, 8 warps (64x64),
// GK=64 (half the chunk boundaries), 3-stage cp.async.
// Epilogue: fp32 g_Z (all rows) + fp16 g_Zh (query rows).
// =====================================================================
#define GM 128
#define GN 256
#define GK 64
#define NCH (F_IN / GK)          // 64
#define ROWB 144                 // 64 fp16 (128B) + 16B pad
#define SA    0
#define SB    (GM * ROWB)                      // 18432
#define STAGE (GM * ROWB + GN * ROWB)          // 55296
#define NSTAGE 3
#define GEMM_SMEM (NSTAGE * STAGE)             // 165888

__device__ __forceinline__ void copy_chunk(uint32_t sb, int blockRow, int blockCol,
                                           int c, int tid)
{
    const size_t kc = (size_t)c * GK;
    // A: 128 rows x 8 segs = 1024 x 16B, 256 thr -> 4 iters
    #pragma unroll
    for (int i = 0; i < 4; i++) {
        const int id  = tid + i * 256;
        const int rid = id >> 3;
        const int seg = id & 7;
        const char* src = (const char*)g_A
                        + ((size_t)(blockRow + rid) * F_IN + kc) * 2 + seg * 16;
        cp_async16(sb + SA + rid * ROWB + seg * 16, src);
    }
    // B: 256 rows x 8 segs = 2048 x 16B -> 8 iters
    #pragma unroll
    for (int i = 0; i < 8; i++) {
        const int id  = tid + i * 256;
        const int rid = id >> 3;
        const int seg = id & 7;
        const char* src = (const char*)g_Wt
                        + ((size_t)(blockCol + rid) * F_IN + kc) * 2 + seg * 16;
        cp_async16(sb + SB + rid * ROWB + seg * 16, src);
    }
}

// one full pass over the 64x64 warp tile: 32 HMMA
#define MMA_PASS(ACC, A, B)                                   \
    _Pragma("unroll")                                         \
    for (int mt = 0; mt < 4; mt++) {                          \
        _Pragma("unroll")                                     \
        for (int p = 0; p < 4; p++) {                         \
            mma_f16(ACC[mt][p * 2 + 0], A[mt], &B[p][0]);     \
            mma_f16(ACC[mt][p * 2 + 1], A[mt], &B[p][2]);     \
        }                                                     \
    }

__global__ __launch_bounds__(256, 1)
void gemm_fp16(const float* __restrict__ bias)
{
    extern __shared__ char smem[];
    const uint32_t sbase = smem_u32(smem);
    const int tid = threadIdx.x;
    const int wid = tid >> 5;
    const int l   = tid & 31;
    const int warpM = wid >> 2;          // 0..1 -> 64-row strip
    const int warpN = wid & 3;           // 0..3 -> 64-col strip
    const int blockRow = blockIdx.y * GM;
    const int blockCol = blockIdx.x * GN;

    const uint32_t aOff = (uint32_t)((warpM * 64 + (l & 15)) * ROWB + (l >> 4) * 16);
    uint32_t bOff[4];
    #pragma unroll
    for (int p = 0; p < 4; p++)
        bOff[p] = (uint32_t)(SB + (warpN * 64 + p * 16 + ((l >> 4) & 1) * 8 + (l & 7)) * ROWB
                             + ((l >> 3) & 1) * 16);

    float acc[4][8][4];
    #pragma unroll
    for (int mt = 0; mt < 4; mt++)
        #pragma unroll
        for (int nt = 0; nt < 8; nt++)
            #pragma unroll
            for (int r = 0; r < 4; r++) acc[mt][nt][r] = 0.f;

    copy_chunk(sbase, blockRow, blockCol, 0, tid);
    cp_commit();
    copy_chunk(sbase + STAGE, blockRow, blockCol, 1, tid);
    cp_commit();

    uint32_t stOff = 0;
    uint32_t wrOff = 2 * STAGE;

    for (int c = 0; c < NCH; c++) {
        cp_wait1();
        __syncthreads();

        if (c + 2 < NCH) copy_chunk(sbase + wrOff, blockRow, blockCol, c + 2, tid);
        cp_commit();

        const uint32_t st = sbase + stOff;
        #pragma unroll
        for (int ks = 0; ks < 4; ks++) {
            const uint32_t kb = ks * 32;
            uint32_t aF[4][4], bF[4][4];

            #pragma unroll
            for (int mt = 0; mt < 4; mt++) ldmx4(aF[mt], st + aOff + mt * (16 * ROWB) + kb);
            #pragma unroll
            for (int p = 0; p < 4; p++)   ldmx4(bF[p], st + bOff[p] + kb);

            MMA_PASS(acc, aF, bF);
        }

        stOff += STAGE; if (stOff == NSTAGE * STAGE) stOff = 0;
        wrOff += STAGE; if (wrOff == NSTAGE * STAGE) wrOff = 0;
    }

    // epilogue: + bias; fp32 g_Z always, fp16 g_Zh for query rows
    const bool isQuery = (blockRow < N_QUERY);
    #pragma unroll
    for (int mt = 0; mt < 4; mt++) {
        const int r0 = blockRow + warpM * 64 + mt * 16 + (l >> 2);
        #pragma unroll
        for (int nt = 0; nt < 8; nt++) {
            const int col = blockCol + warpN * 64 + nt * 8 + (l & 3) * 2;
            const float b0 = bias[col], b1 = bias[col + 1];
            const float v00 = acc[mt][nt][0] + b0, v01 = acc[mt][nt][1] + b1;
            const float v10 = acc[mt][nt][2] + b0, v11 = acc[mt][nt][3] + b1;
            *(float2*)(g_Z + (size_t)r0 * D_EMB + col)       = make_float2(v00, v01);
            *(float2*)(g_Z + (size_t)(r0 + 8) * D_EMB + col) = make_float2(v10, v11);
            if (isQuery) {
                __half2 h0, h1;
                h0.x = __float2half_rn(v00); h0.y = __float2half_rn(v01);
                h1.x = __float2half_rn(v10); h1.y = __float2half_rn(v11);
                *(__half2*)(g_Zh + (size_t)r0 * D_EMB + col)       = h0;
                *(__half2*)(g_Zh + (size_t)(r0 + 8) * D_EMB + col) = h1;
            }
        }
    }
}

// =====================================================================
// Kernel E: prototypes (lower median + mean), inline stable-order scan,
// class stats; emits fp16 prototypes. One block per class (128 blocks).
// =====================================================================
__global__ __launch_bounds__(256)
void proto_kernel(const int* __restrict__ labels)
{
    const int c   = blockIdx.x;
    const int tid = threadIdx.x;
    const int l   = tid & 31;
    __shared__ float s_sum[256], s_sum2[256];
    __shared__ int   s_idx[K_SHOT];

    if (c < N_WAY && tid < 32) {
        int base = 0;
        for (int i0 = 0; i0 < N_SUPPORT; i0 += 32) {
            const int i = i0 + l;
            const bool match = (i < N_SUPPORT) && (labels[i] == c);
            const unsigned m = __ballot_sync(0xFFFFFFFFu, match);
            if (match) {
                const int pos = base + __popc(m & ((1u << l) - 1u));
                if (pos < K_SHOT) s_idx[pos] = i;
            }
            base += __popc(m);
        }
    }
    __syncthreads();

    float psum = 0.f, psum2 = 0.f;
    if (c < N_WAY) {
        int idx[K_SHOT];
        #pragma unroll
        for (int j = 0; j < K_SHOT; j++) idx[j] = s_idx[j];

        for (int d = tid; d < D_EMB; d += 256) {
            float v[K_SHOT];
            #pragma unroll
            for (int j = 0; j < K_SHOT; j++)
                v[j] = g_Z[(size_t)(N_QUERY + idx[j]) * D_EMB + d];

            float mean = 0.f;
            #pragma unroll
            for (int j = 0; j < K_SHOT; j++) mean += v[j];
            mean *= (1.0f / K_SHOT);

            #pragma unroll
            for (int p = 0; p < K_SHOT - 1; p++)
                #pragma unroll
                for (int q = 0; q < K_SHOT - 1 - p; q++) {
                    float lo = fminf(v[q], v[q + 1]);
                    float hi = fmaxf(v[q], v[q + 1]);
                    v[q] = lo; v[q + 1] = hi;
                }
            const float med = v[(K_SHOT - 1) / 2];
            const float zt  = 0.5f * (med + mean);
            g_Ph[(size_t)c * D_EMB + d] = __float2half_rn(zt);
            psum += zt; psum2 += zt * zt;
        }
    } else {
        for (int d = tid; d < D_EMB; d += 256)
            g_Ph[(size_t)c * D_EMB + d] = __float2half_rn(0.f);
    }

    s_sum[tid] = psum; s_sum2[tid] = psum2;
    __syncthreads();
    for (int s = 128; s > 0; s >>= 1) {
        if (tid < s) { s_sum[tid] += s_sum[tid + s]; s_sum2[tid] += s_sum2[tid + s]; }
        __syncthreads();
    }
    if (tid == 0 && c < N_WAY) { g_ps[c] = s_sum[0]; g_p2[c] = s_sum2[0]; }
}

// =====================================================================
// Kernel F: per-query-row sum / sum-of-squares — warp per row (fp32)
// =====================================================================
__global__ __launch_bounds__(256)
void qstats_kernel()
{
    const int warp = (blockIdx.x * blockDim.x + threadIdx.x) >> 5;
    const int l    = threadIdx.x & 31;
    if (warp >= N_QUERY) return;
    const float* z = g_Z + (size_t)warp * D_EMB;
    float s = 0.f, s2 = 0.f;
    #pragma unroll
    for (int i = 0; i < 8; i++) {
        float4 v = *(const float4*)(z + (l + i * 32) * 4);
        s  += v.x + v.y + v.z + v.w;
        s2 += v.x * v.x + v.y * v.y + v.z * v.z + v.w * v.w;
    }
    #pragma unroll
    for (int off = 16; off > 0; off >>= 1) {
        s  += __shfl_xor_sync(0xFFFFFFFFu, s,  off);
        s2 += __shfl_xor_sync(0xFFFFFFFFu, s2, off);
    }
    if (l == 0) { g_qs[warp] = s; g_q2[warp] = s2; }
}

// =====================================================================
// Kernel G: distance matrix — fp16 mma GEMM (128 x 128pad x 1024) with
// fused PairwiseDistance-eps epilogue. 8 warps, warp tile 32x64,
// 2-stage cp.async.
// =====================================================================
#define D2K 64
#define NCH2 (D_EMB / D2K)                  // 16
#define S2A 0
#define S2B (128 * ROWB)                    // 18432
#define STAGE2 (2 * 128 * ROWB)             // 36864
#define DIST_SMEM (2 * STAGE2)              // 73728

__device__ __forceinline__ void copy_chunk2(uint32_t sb, int blockRow, int c, int tid)
{
    const size_t kb = (size_t)c * D2K * 2;   // byte offset within a row
    #pragma unroll
    for (int i = 0; i < 4; i++) {            // A: 128 rows x 8 segs
        const int id = tid + i * 256, rid = id >> 3, seg = id & 7;
        cp_async16(sb + S2A + rid * ROWB + seg * 16,
                   (const char*)g_Zh + ((size_t)(blockRow + rid) * D_EMB) * 2 + kb + seg * 16);
    }
    #pragma unroll
    for (int i = 0; i < 4; i++) {            // B: 128 rows x 8 segs
        const int id = tid + i * 256, rid = id >> 3, seg = id & 7;
        cp_async16(sb + S2B + rid * ROWB + seg * 16,
                   (const char*)g_Ph + ((size_t)rid * D_EMB) * 2 + kb + seg * 16);
    }
}

__global__ __launch_bounds__(256, 1)
void dist_mma_kernel(float* __restrict__ out)
{
    extern __shared__ char smem[];
    const uint32_t sbase = smem_u32(smem);
    const int tid = threadIdx.x;
    const int wid = tid >> 5;
    const int l   = tid & 31;
    const int warpM = wid >> 1;          // 0..3 -> 32-row strip
    const int warpN = wid & 1;           // 0..1 -> 64-col strip
    const int blockRow = blockIdx.x * 128;

    const uint32_t aOff = (uint32_t)((warpM * 32 + (l & 15)) * ROWB + (l >> 4) * 16);
    uint32_t bOff[4];
    #pragma unroll
    for (int p = 0; p < 4; p++)
        bOff[p] = (uint32_t)(S2B + (warpN * 64 + p * 16 + ((l >> 4) & 1) * 8 + (l & 7)) * ROWB
                             + ((l >> 3) & 1) * 16);

    float acc[2][8][4];
    #pragma unroll
    for (int mt = 0; mt < 2; mt++)
        #pragma unroll
        for (int nt = 0; nt < 8; nt++)
            #pragma unroll
            for (int r = 0; r < 4; r++) acc[mt][nt][r] = 0.f;

    copy_chunk2(sbase, blockRow, 0, tid);
    cp_commit();

    for (int c = 0; c < NCH2; c++) {
        cp_wait0();
        __syncthreads();
        if (c + 1 < NCH2)
            copy_chunk2(sbase + (uint32_t)((c + 1) & 1) * STAGE2, blockRow, c + 1, tid);
        cp_commit();

        const uint32_t st = sbase + (uint32_t)(c & 1) * STAGE2;
        #pragma unroll
        for (int ks = 0; ks < 4; ks++) {
            const uint32_t kb = ks * 32;
            uint32_t aF[2][4], bF[4][4];

            #pragma unroll
            for (int mt = 0; mt < 2; mt++) ldmx4(aF[mt], st + aOff + mt * (16 * ROWB) + kb);
            #pragma unroll
            for (int p = 0; p < 4; p++)   ldmx4(bF[p], st + bOff[p] + kb);

            #pragma unroll
            for (int mt = 0; mt < 2; mt++)
                #pragma unroll
                for (int p = 0; p < 4; p++) {
                    mma_f16(acc[mt][p * 2 + 0], aF[mt], &bF[p][0]);
                    mma_f16(acc[mt][p * 2 + 1], aF[mt], &bF[p][2]);
                }
        }
        __syncthreads();   // stage c&1 fully consumed before it is refilled
    }

    // fused distance epilogue
    const float deps2 = (float)D_EMB * EPS_F * EPS_F;
    #pragma unroll
    for (int mt = 0; mt < 2; mt++) {
        const int r0 = blockRow + warpM * 32 + mt * 16 + (l >> 2);
        const float q2a = g_q2[r0],     qsa = g_qs[r0];
        const float q2b = g_q2[r0 + 8], qsb = g_qs[r0 + 8];
        #pragma unroll
        for (int nt = 0; nt < 8; nt++) {
            const int c0 = warpN * 64 + nt * 8 + (l & 3) * 2;
            #pragma unroll
            for (int jj = 0; jj < 2; jj++) {
                const int c = c0 + jj;
                if (c < N_WAY) {
                    const float p2v = g_p2[c], psv = g_ps[c];
                    float sqa = q2a + p2v - 2.0f * acc[mt][nt][jj]
                              + 2.0f * EPS_F * (qsa - psv) + deps2;
                    float sqb = q2b + p2v - 2.0f * acc[mt][nt][2 + jj]
                              + 2.0f * EPS_F * (qsb - psv) + deps2;
                    out[(size_t)r0 * N_WAY + c]       = -sqrtf(fmaxf(sqa, 0.0f));
                    out[(size_t)(r0 + 8) * N_WAY + c] = -sqrtf(fmaxf(sqb, 0.0f));
                }
            }
        }
    }
}

// =====================================================================
// launch
// =====================================================================
extern "C" void kernel_launch(void* const* d_in, const int* in_sizes, int n_in,
                              void* d_out, int out_size)
{
    const float* support = (const float*)d_in[0];
    const int*   labels  = (const int*)  d_in[1];
    const float* query   = (const float*)d_in[2];
    const float* W       = (const float*)d_in[3];
    const float* b       = (const float*)d_in[4];
    float*       out     = (float*)d_out;

    cudaFuncSetAttribute(gemm_fp16,
                         cudaFuncAttributeMaxDynamicSharedMemorySize, GEMM_SMEM);
    cudaFuncSetAttribute(dist_mma_kernel,
                         cudaFuncAttributeMaxDynamicSharedMemorySize, DIST_SMEM);

    {
        const size_t total = (size_t)M_TOT * F_IN / 4;
        convert_A<<<(unsigned)((total + 255) / 256), 256>>>(query, support);
    }
    convert_W<<<dim3(F_IN / 32, D_EMB / 32), dim3(32, 8)>>>(W);

    gemm_fp16<<<dim3(D_EMB / GN, M_TOT / GM), 256, GEMM_SMEM>>>(b);

    proto_kernel<<<128, 256>>>(labels);
    qstats_kernel<<<N_QUERY / 8, 256>>>();
    dist_mma_kernel<<<N_QUERY / 128, 256, DIST_SMEM>>>(out);
}

// round 14
// speedup vs baseline: 2.8552x; 1.0898x over previous
#include <cuda_runtime.h>
#include <cuda_fp16.h>
#include <math.h>
#include <stdint.h>

#define N_WAY     100
#define K_SHOT    10
#define N_SUPPORT 1000
#define N_QUERY   8192
#define F_IN      4096
#define D_EMB     1024
#define EPS_F     1e-6f

#define M_TOT     9216   // 8192 query rows + 1000 support + 24 pad

// ---------------- scratch (static device globals; no allocations) ----------
__device__ __half g_Wt[(size_t)D_EMB * F_IN];       // W transposed, fp16
__device__ float  g_Z[(size_t)M_TOT * D_EMB];       // fp32 embeddings (support rows)
__device__ __half g_Zh[(size_t)N_QUERY * D_EMB];    // fp16 query embeddings
__device__ __half g_Ph[128 * D_EMB];                // fp16 prototypes (pad 128)
__device__ float g_p2[128];
__device__ float g_ps[128];
__device__ float g_q2[N_QUERY];
__device__ float g_qs[N_QUERY];

// ======================= portable PTX helpers ==============================
__device__ __forceinline__ uint32_t smem_u32(const void* p) {
    uint32_t a;
    asm("{ .reg .u64 t; cvta.to.shared.u64 t, %1; cvt.u32.u64 %0, t; }"
        : "=r"(a) : "l"(p));
    return a;
}
__device__ __forceinline__ void cp_async16(uint32_t dst, const void* src) {
    asm volatile("cp.async.cg.shared.global [%0], [%1], 16;"
                 :: "r"(dst), "l"(src) : "memory");
}
__device__ __forceinline__ void cp_commit() {
    asm volatile("cp.async.commit_group;" ::: "memory");
}
__device__ __forceinline__ void cp_wait1() {
    asm volatile("cp.async.wait_group 1;" ::: "memory");
}
__device__ __forceinline__ void cp_wait0() {
    asm volatile("cp.async.wait_group 0;" ::: "memory");
}
__device__ __forceinline__ void ldmx4(uint32_t* r, uint32_t addr) {
    asm volatile("ldmatrix.sync.aligned.m8n8.x4.shared.b16 {%0,%1,%2,%3}, [%4];"
                 : "=r"(r[0]), "=r"(r[1]), "=r"(r[2]), "=r"(r[3]) : "r"(addr));
}
__device__ __forceinline__ void mma_f16(float* c, const uint32_t* a, const uint32_t* b) {
    asm volatile(
        "mma.sync.aligned.m16n8k16.row.col.f32.f16.f16.f32 "
        "{%0,%1,%2,%3}, {%4,%5,%6,%7}, {%8,%9}, {%0,%1,%2,%3};"
        : "+f"(c[0]), "+f"(c[1]), "+f"(c[2]), "+f"(c[3])
        : "r"(a[0]), "r"(a[1]), "r"(a[2]), "r"(a[3]), "r"(b[0]), "r"(b[1]));
}

// =====================================================================
// Kernel B: transpose W [4096,1024] -> Wt [1024,4096] fp16
// =====================================================================
__global__ void convert_W(const float* __restrict__ W)
{
    __shared__ __half th[32][33];
    const int k0 = blockIdx.x * 32, n0 = blockIdx.y * 32;
    const int tx = threadIdx.x, ty = threadIdx.y;   // (32, 8)
    #pragma unroll
    for (int i = 0; i < 4; i++) {
        const int kk = ty + i * 8;
        th[kk][tx] = __float2half_rn(W[(size_t)(k0 + kk) * D_EMB + n0 + tx]);
    }
    __syncthreads();
    #pragma unroll
    for (int i = 0; i < 4; i++) {
        const int nn = ty + i * 8;
        g_Wt[(size_t)(n0 + nn) * F_IN + k0 + tx] = th[tx][nn];
    }
}

// =====================================================================
// Kernel C: single-pass fp16 GEMM with FUSED fp32->fp16 A conversion.
// 128x256 tile, 8 warps (64x64), GK=64, 3-stage.
// A: LDG fp32 (chunk c+2) at loop top -> regs -> fp16 STS at loop bottom.
// B: cp.async fp16 from g_Wt.
// Epilogue: query rows -> fp16 g_Zh only; support rows -> fp32 g_Z.
// =====================================================================
#define GM 128
#define GN 256
#define GK 64
#define NCH (F_IN / GK)          // 64
#define ROWB 144                 // 64 fp16 (128B) + 16B pad
#define SA    0
#define SB    (GM * ROWB)                      // 18432
#define STAGE (GM * ROWB + GN * ROWB)          // 55296
#define NSTAGE 3
#define GEMM_SMEM (NSTAGE * STAGE)             // 165888

// load fp32 A strip for chunk c into registers (8 floats per thread-iter)
__device__ __forceinline__ void ldgA(float4 av[4][2],
                                     const float* __restrict__ q,
                                     const float* __restrict__ s,
                                     int blockRow, int c, int tid)
{
    const int kc = c * GK;
    #pragma unroll
    for (int i = 0; i < 4; i++) {
        const int id  = tid + i * 256;
        const int rid = id >> 3;         // 0..127
        const int seg = id & 7;          // 0..7 (8 fp32 each)
        const int r   = blockRow + rid;
        if (r < N_QUERY) {
            const float* src = q + (size_t)r * F_IN + kc + seg * 8;
            av[i][0] = *(const float4*)(src);
            av[i][1] = *(const float4*)(src + 4);
        } else if (r < N_QUERY + N_SUPPORT) {
            const float* src = s + (size_t)(r - N_QUERY) * F_IN + kc + seg * 8;
            av[i][0] = *(const float4*)(src);
            av[i][1] = *(const float4*)(src + 4);
        } else {
            av[i][0] = make_float4(0.f, 0.f, 0.f, 0.f);
            av[i][1] = make_float4(0.f, 0.f, 0.f, 0.f);
        }
    }
}

// convert register strip to fp16 and store into smem stage
__device__ __forceinline__ void stsA(char* stagePtr, const float4 av[4][2], int tid)
{
    #pragma unroll
    for (int i = 0; i < 4; i++) {
        const int id  = tid + i * 256;
        const int rid = id >> 3;
        const int seg = id & 7;
        union { __half h[8]; uint4 u; } pk;
        const float* f = (const float*)&av[i][0];
        #pragma unroll
        for (int j = 0; j < 8; j++) pk.h[j] = __float2half_rn(f[j]);
        *(uint4*)(stagePtr + SA + rid * ROWB + seg * 16) = pk.u;
    }
}

__device__ __forceinline__ void copy_B(uint32_t sb, int blockCol, int c, int tid)
{
    const size_t kc = (size_t)c * GK;
    #pragma unroll
    for (int i = 0; i < 8; i++) {
        const int id  = tid + i * 256;
        const int rid = id >> 3;
        const int seg = id & 7;
        const char* src = (const char*)g_Wt
                        + ((size_t)(blockCol + rid) * F_IN + kc) * 2 + seg * 16;
        cp_async16(sb + SB + rid * ROWB + seg * 16, src);
    }
}

// one full pass over the 64x64 warp tile: 32 HMMA
#define MMA_PASS(ACC, A, B)                                   \
    _Pragma("unroll")                                         \
    for (int mt = 0; mt < 4; mt++) {                          \
        _Pragma("unroll")                                     \
        for (int p = 0; p < 4; p++) {                         \
            mma_f16(ACC[mt][p * 2 + 0], A[mt], &B[p][0]);     \
            mma_f16(ACC[mt][p * 2 + 1], A[mt], &B[p][2]);     \
        }                                                     \
    }

__global__ __launch_bounds__(256, 1)
void gemm_fp16(const float* __restrict__ q, const float* __restrict__ s,
               const float* __restrict__ bias)
{
    extern __shared__ char smem[];
    const uint32_t sbase = smem_u32(smem);
    const int tid = threadIdx.x;
    const int wid = tid >> 5;
    const int l   = tid & 31;
    const int warpM = wid >> 2;          // 0..1 -> 64-row strip
    const int warpN = wid & 3;           // 0..3 -> 64-col strip
    const int blockRow = blockIdx.y * GM;
    const int blockCol = blockIdx.x * GN;

    const uint32_t aOff = (uint32_t)((warpM * 64 + (l & 15)) * ROWB + (l >> 4) * 16);
    uint32_t bOff[4];
    #pragma unroll
    for (int p = 0; p < 4; p++)
        bOff[p] = (uint32_t)(SB + (warpN * 64 + p * 16 + ((l >> 4) & 1) * 8 + (l & 7)) * ROWB
                             + ((l >> 3) & 1) * 16);

    float acc[4][8][4];
    #pragma unroll
    for (int mt = 0; mt < 4; mt++)
        #pragma unroll
        for (int nt = 0; nt < 8; nt++)
            #pragma unroll
            for (int r = 0; r < 4; r++) acc[mt][nt][r] = 0.f;

    // prologue: A chunks 0,1 synchronous LDG->STS; B chunks 0,1 cp.async
    {
        float4 av[4][2];
        ldgA(av, q, s, blockRow, 0, tid); stsA(smem, av, tid);
        ldgA(av, q, s, blockRow, 1, tid); stsA(smem + STAGE, av, tid);
    }
    copy_B(sbase, blockCol, 0, tid);
    cp_commit();
    copy_B(sbase + STAGE, blockCol, 1, tid);
    cp_commit();

    uint32_t stOff = 0;
    uint32_t wrOff = 2 * STAGE;

    for (int c = 0; c < NCH; c++) {
        const bool pf = (c + 2 < NCH);
        float4 av[4][2];
        if (pf) ldgA(av, q, s, blockRow, c + 2, tid);   // LDG issued early, no stall

        cp_wait1();
        __syncthreads();

        if (pf) copy_B(sbase + wrOff, blockCol, c + 2, tid);
        cp_commit();

        const uint32_t st = sbase + stOff;
        #pragma unroll
        for (int ks = 0; ks < 4; ks++) {
            const uint32_t kb = ks * 32;
            uint32_t aF[4][4], bF[4][4];

            #pragma unroll
            for (int mt = 0; mt < 4; mt++) ldmx4(aF[mt], st + aOff + mt * (16 * ROWB) + kb);
            #pragma unroll
            for (int p = 0; p < 4; p++)   ldmx4(bF[p], st + bOff[p] + kb);

            MMA_PASS(acc, aF, bF);
        }

        if (pf) stsA(smem + wrOff, av, tid);   // convert+store after MMAs (LDG complete)

        stOff += STAGE; if (stOff == NSTAGE * STAGE) stOff = 0;
        wrOff += STAGE; if (wrOff == NSTAGE * STAGE) wrOff = 0;
    }

    // epilogue: + bias; query rows -> fp16 g_Zh; support rows -> fp32 g_Z
    const bool isQuery = (blockRow < N_QUERY);
    #pragma unroll
    for (int mt = 0; mt < 4; mt++) {
        const int r0 = blockRow + warpM * 64 + mt * 16 + (l >> 2);
        #pragma unroll
        for (int nt = 0; nt < 8; nt++) {
            const int col = blockCol + warpN * 64 + nt * 8 + (l & 3) * 2;
            const float b0 = bias[col], b1 = bias[col + 1];
            const float v00 = acc[mt][nt][0] + b0, v01 = acc[mt][nt][1] + b1;
            const float v10 = acc[mt][nt][2] + b0, v11 = acc[mt][nt][3] + b1;
            if (isQuery) {
                __half2 h0, h1;
                h0.x = __float2half_rn(v00); h0.y = __float2half_rn(v01);
                h1.x = __float2half_rn(v10); h1.y = __float2half_rn(v11);
                *(__half2*)(g_Zh + (size_t)r0 * D_EMB + col)       = h0;
                *(__half2*)(g_Zh + (size_t)(r0 + 8) * D_EMB + col) = h1;
            } else {
                *(float2*)(g_Z + (size_t)r0 * D_EMB + col)       = make_float2(v00, v01);
                *(float2*)(g_Z + (size_t)(r0 + 8) * D_EMB + col) = make_float2(v10, v11);
            }
        }
    }
}

// =====================================================================
// Kernel E: prototypes — 1024 threads (one per dim), one block per class.
// Inline stable-order scan (warp 0), lower median + mean, fp16 output.
// =====================================================================
__global__ __launch_bounds__(1024)
void proto_kernel(const int* __restrict__ labels)
{
    const int c   = blockIdx.x;      // 0..127
    const int tid = threadIdx.x;     // 0..1023 == dim
    const int l   = tid & 31;
    __shared__ float s_sum[1024], s_sum2[1024];
    __shared__ int   s_idx[K_SHOT];

    if (c < N_WAY && tid < 32) {
        int base = 0;
        for (int i0 = 0; i0 < N_SUPPORT; i0 += 32) {
            const int i = i0 + l;
            const bool match = (i < N_SUPPORT) && (labels[i] == c);
            const unsigned m = __ballot_sync(0xFFFFFFFFu, match);
            if (match) {
                const int pos = base + __popc(m & ((1u << l) - 1u));
                if (pos < K_SHOT) s_idx[pos] = i;
            }
            base += __popc(m);
        }
    }
    __syncthreads();

    float psum = 0.f, psum2 = 0.f;
    if (c < N_WAY) {
        float v[K_SHOT];
        #pragma unroll
        for (int j = 0; j < K_SHOT; j++)
            v[j] = g_Z[(size_t)(N_QUERY + s_idx[j]) * D_EMB + tid];

        float mean = 0.f;
        #pragma unroll
        for (int j = 0; j < K_SHOT; j++) mean += v[j];
        mean *= (1.0f / K_SHOT);

        #pragma unroll
        for (int p = 0; p < K_SHOT - 1; p++)
            #pragma unroll
            for (int qq = 0; qq < K_SHOT - 1 - p; qq++) {
                float lo = fminf(v[qq], v[qq + 1]);
                float hi = fmaxf(v[qq], v[qq + 1]);
                v[qq] = lo; v[qq + 1] = hi;
            }
        const float med = v[(K_SHOT - 1) / 2];
        const float zt  = 0.5f * (med + mean);
        g_Ph[(size_t)c * D_EMB + tid] = __float2half_rn(zt);
        psum = zt; psum2 = zt * zt;
    } else {
        g_Ph[(size_t)c * D_EMB + tid] = __float2half_rn(0.f);
    }

    s_sum[tid] = psum; s_sum2[tid] = psum2;
    __syncthreads();
    for (int st = 512; st > 0; st >>= 1) {
        if (tid < st) { s_sum[tid] += s_sum[tid + st]; s_sum2[tid] += s_sum2[tid + st]; }
        __syncthreads();
    }
    if (tid == 0 && c < N_WAY) { g_ps[c] = s_sum[0]; g_p2[c] = s_sum2[0]; }
}

// =====================================================================
// Kernel F: per-query-row stats from fp16 g_Zh — warp per row
// =====================================================================
__global__ __launch_bounds__(256)
void qstats_kernel()
{
    const int warp = (blockIdx.x * blockDim.x + threadIdx.x) >> 5;
    const int l    = threadIdx.x & 31;
    if (warp >= N_QUERY) return;
    const __half* z = g_Zh + (size_t)warp * D_EMB;
    float s = 0.f, s2 = 0.f;
    #pragma unroll
    for (int i = 0; i < 4; i++) {
        uint4 u = *(const uint4*)(z + ((size_t)l + i * 32) * 8);
        const uint32_t w[4] = {u.x, u.y, u.z, u.w};
        #pragma unroll
        for (int j = 0; j < 4; j++) {
            float2 f = __half22float2(*(const __half2*)&w[j]);
            s  += f.x + f.y;
            s2 += f.x * f.x + f.y * f.y;
        }
    }
    #pragma unroll
    for (int off = 16; off > 0; off >>= 1) {
        s  += __shfl_xor_sync(0xFFFFFFFFu, s,  off);
        s2 += __shfl_xor_sync(0xFFFFFFFFu, s2, off);
    }
    if (l == 0) { g_qs[warp] = s; g_q2[warp] = s2; }
}

// =====================================================================
// Kernel G: distance matrix — fp16 mma GEMM (128 x 128pad x 1024) with
// fused PairwiseDistance-eps epilogue. 8 warps, warp tile 32x64, 2-stage.
// =====================================================================
#define D2K 64
#define NCH2 (D_EMB / D2K)                  // 16
#define S2A 0
#define S2B (128 * ROWB)                    // 18432
#define STAGE2 (2 * 128 * ROWB)             // 36864
#define DIST_SMEM (2 * STAGE2)              // 73728

__device__ __forceinline__ void copy_chunk2(uint32_t sb, int blockRow, int c, int tid)
{
    const size_t kb = (size_t)c * D2K * 2;
    #pragma unroll
    for (int i = 0; i < 4; i++) {            // A: 128 rows x 8 segs
        const int id = tid + i * 256, rid = id >> 3, seg = id & 7;
        cp_async16(sb + S2A + rid * ROWB + seg * 16,
                   (const char*)g_Zh + ((size_t)(blockRow + rid) * D_EMB) * 2 + kb + seg * 16);
    }
    #pragma unroll
    for (int i = 0; i < 4; i++) {            // B: 128 rows x 8 segs
        const int id = tid + i * 256, rid = id >> 3, seg = id & 7;
        cp_async16(sb + S2B + rid * ROWB + seg * 16,
                   (const char*)g_Ph + ((size_t)rid * D_EMB) * 2 + kb + seg * 16);
    }
}

__global__ __launch_bounds__(256, 1)
void dist_mma_kernel(float* __restrict__ out)
{
    extern __shared__ char smem[];
    const uint32_t sbase = smem_u32(smem);
    const int tid = threadIdx.x;
    const int wid = tid >> 5;
    const int l   = tid & 31;
    const int warpM = wid >> 1;          // 0..3 -> 32-row strip
    const int warpN = wid & 1;           // 0..1 -> 64-col strip
    const int blockRow = blockIdx.x * 128;

    const uint32_t aOff = (uint32_t)((warpM * 32 + (l & 15)) * ROWB + (l >> 4) * 16);
    uint32_t bOff[4];
    #pragma unroll
    for (int p = 0; p < 4; p++)
        bOff[p] = (uint32_t)(S2B + (warpN * 64 + p * 16 + ((l >> 4) & 1) * 8 + (l & 7)) * ROWB
                             + ((l >> 3) & 1) * 16);

    float acc[2][8][4];
    #pragma unroll
    for (int mt = 0; mt < 2; mt++)
        #pragma unroll
        for (int nt = 0; nt < 8; nt++)
            #pragma unroll
            for (int r = 0; r < 4; r++) acc[mt][nt][r] = 0.f;

    copy_chunk2(sbase, blockRow, 0, tid);
    cp_commit();

    for (int c = 0; c < NCH2; c++) {
        cp_wait0();
        __syncthreads();
        if (c + 1 < NCH2)
            copy_chunk2(sbase + (uint32_t)((c + 1) & 1) * STAGE2, blockRow, c + 1, tid);
        cp_commit();

        const uint32_t st = sbase + (uint32_t)(c & 1) * STAGE2;
        #pragma unroll
        for (int ks = 0; ks < 4; ks++) {
            const uint32_t kb = ks * 32;
            uint32_t aF[2][4], bF[4][4];

            #pragma unroll
            for (int mt = 0; mt < 2; mt++) ldmx4(aF[mt], st + aOff + mt * (16 * ROWB) + kb);
            #pragma unroll
            for (int p = 0; p < 4; p++)   ldmx4(bF[p], st + bOff[p] + kb);

            #pragma unroll
            for (int mt = 0; mt < 2; mt++)
                #pragma unroll
                for (int p = 0; p < 4; p++) {
                    mma_f16(acc[mt][p * 2 + 0], aF[mt], &bF[p][0]);
                    mma_f16(acc[mt][p * 2 + 1], aF[mt], &bF[p][2]);
                }
        }
        __syncthreads();   // stage c&1 fully consumed before refill
    }

    // fused distance epilogue
    const float deps2 = (float)D_EMB * EPS_F * EPS_F;
    #pragma unroll
    for (int mt = 0; mt < 2; mt++) {
        const int r0 = blockRow + warpM * 32 + mt * 16 + (l >> 2);
        const float q2a = g_q2[r0],     qsa = g_qs[r0];
        const float q2b = g_q2[r0 + 8], qsb = g_qs[r0 + 8];
        #pragma unroll
        for (int nt = 0; nt < 8; nt++) {
            const int c0 = warpN * 64 + nt * 8 + (l & 3) * 2;
            #pragma unroll
            for (int jj = 0; jj < 2; jj++) {
                const int c = c0 + jj;
                if (c < N_WAY) {
                    const float p2v = g_p2[c], psv = g_ps[c];
                    float sqa = q2a + p2v - 2.0f * acc[mt][nt][jj]
                              + 2.0f * EPS_F * (qsa - psv) + deps2;
                    float sqb = q2b + p2v - 2.0f * acc[mt][nt][2 + jj]
                              + 2.0f * EPS_F * (qsb - psv) + deps2;
                    out[(size_t)r0 * N_WAY + c]       = -sqrtf(fmaxf(sqa, 0.0f));
                    out[(size_t)(r0 + 8) * N_WAY + c] = -sqrtf(fmaxf(sqb, 0.0f));
                }
            }
        }
    }
}

// =====================================================================
// launch
// =====================================================================
extern "C" void kernel_launch(void* const* d_in, const int* in_sizes, int n_in,
                              void* d_out, int out_size)
{
    const float* support = (const float*)d_in[0];
    const int*   labels  = (const int*)  d_in[1];
    const float* query   = (const float*)d_in[2];
    const float* W       = (const float*)d_in[3];
    const float* b       = (const float*)d_in[4];
    float*       out     = (float*)d_out;

    cudaFuncSetAttribute(gemm_fp16,
                         cudaFuncAttributeMaxDynamicSharedMemorySize, GEMM_SMEM);
    cudaFuncSetAttribute(dist_mma_kernel,
                         cudaFuncAttributeMaxDynamicSharedMemorySize, DIST_SMEM);

    convert_W<<<dim3(F_IN / 32, D_EMB / 32), dim3(32, 8)>>>(W);

    gemm_fp16<<<dim3(D_EMB / GN, M_TOT / GM), 256, GEMM_SMEM>>>(query, support, b);

    proto_kernel<<<128, 1024>>>(labels);
    qstats_kernel<<<N_QUERY / 8, 256>>>();
    dist_mma_kernel<<<N_QUERY / 128, 256, DIST_SMEM>>>(out);
}

// round 15
// speedup vs baseline: 2.9781x; 1.0430x over previous
#include <cuda_runtime.h>
#include <cuda_fp16.h>
#include <math.h>
#include <stdint.h>

#define N_WAY     100
#define K_SHOT    10
#define N_SUPPORT 1000
#define N_QUERY   8192
#define F_IN      4096
#define D_EMB     1024
#define EPS_F     1e-6f

#define M_TOT     9216   // 8192 query rows + 1000 support + 24 pad

// ---------------- scratch (static device globals; no allocations) ----------
__device__ __half g_Wt[(size_t)D_EMB * F_IN];       // W transposed, fp16
__device__ float  g_Z[(size_t)M_TOT * D_EMB];       // fp32 embeddings (support rows)
__device__ __half g_Zh[(size_t)N_QUERY * D_EMB];    // fp16 query embeddings
__device__ __half g_Ph[128 * D_EMB];                // fp16 prototypes (pad 128)
__device__ float g_p2[128];
__device__ float g_ps[128];
__device__ float g_q2[N_QUERY];
__device__ float g_qs[N_QUERY];
__device__ float g_qs_p[16][N_QUERY];               // per-(Nblock,warpN) partial sums
__device__ float g_q2_p[16][N_QUERY];

// ======================= portable PTX helpers ==============================
__device__ __forceinline__ uint32_t smem_u32(const void* p) {
    uint32_t a;
    asm("{ .reg .u64 t; cvta.to.shared.u64 t, %1; cvt.u32.u64 %0, t; }"
        : "=r"(a) : "l"(p));
    return a;
}
__device__ __forceinline__ void cp_async16(uint32_t dst, const void* src) {
    asm volatile("cp.async.cg.shared.global [%0], [%1], 16;"
                 :: "r"(dst), "l"(src) : "memory");
}
__device__ __forceinline__ void cp_commit() {
    asm volatile("cp.async.commit_group;" ::: "memory");
}
__device__ __forceinline__ void cp_wait1() {
    asm volatile("cp.async.wait_group 1;" ::: "memory");
}
__device__ __forceinline__ void cp_wait0() {
    asm volatile("cp.async.wait_group 0;" ::: "memory");
}
__device__ __forceinline__ void ldmx4(uint32_t* r, uint32_t addr) {
    asm volatile("ldmatrix.sync.aligned.m8n8.x4.shared.b16 {%0,%1,%2,%3}, [%4];"
                 : "=r"(r[0]), "=r"(r[1]), "=r"(r[2]), "=r"(r[3]) : "r"(addr));
}
__device__ __forceinline__ void mma_f16(float* c, const uint32_t* a, const uint32_t* b) {
    asm volatile(
        "mma.sync.aligned.m16n8k16.row.col.f32.f16.f16.f32 "
        "{%0,%1,%2,%3}, {%4,%5,%6,%7}, {%8,%9}, {%0,%1,%2,%3};"
        : "+f"(c[0]), "+f"(c[1]), "+f"(c[2]), "+f"(c[3])
        : "r"(a[0]), "r"(a[1]), "r"(a[2]), "r"(a[3]), "r"(b[0]), "r"(b[1]));
}

// =====================================================================
// Kernel B: transpose W [4096,1024] -> Wt [1024,4096] fp16
// =====================================================================
__global__ void convert_W(const float* __restrict__ W)
{
    __shared__ __half th[32][33];
    const int k0 = blockIdx.x * 32, n0 = blockIdx.y * 32;
    const int tx = threadIdx.x, ty = threadIdx.y;   // (32, 8)
    #pragma unroll
    for (int i = 0; i < 4; i++) {
        const int kk = ty + i * 8;
        th[kk][tx] = __float2half_rn(W[(size_t)(k0 + kk) * D_EMB + n0 + tx]);
    }
    __syncthreads();
    #pragma unroll
    for (int i = 0; i < 4; i++) {
        const int nn = ty + i * 8;
        g_Wt[(size_t)(n0 + nn) * F_IN + k0 + tx] = th[tx][nn];
    }
}

// =====================================================================
// Kernel C: single-pass fp16 GEMM with fused A conversion AND fused
// per-row sum/sum-of-squares partials for query rows.
// =====================================================================
#define GM 128
#define GN 256
#define GK 64
#define NCH (F_IN / GK)          // 64
#define ROWB 144                 // 64 fp16 (128B) + 16B pad
#define SA    0
#define SB    (GM * ROWB)                      // 18432
#define STAGE (GM * ROWB + GN * ROWB)          // 55296
#define NSTAGE 3
#define GEMM_SMEM (NSTAGE * STAGE)             // 165888

__device__ __forceinline__ void ldgA(float4 av[4][2],
                                     const float* __restrict__ q,
                                     const float* __restrict__ s,
                                     int blockRow, int c, int tid)
{
    const int kc = c * GK;
    #pragma unroll
    for (int i = 0; i < 4; i++) {
        const int id  = tid + i * 256;
        const int rid = id >> 3;
        const int seg = id & 7;
        const int r   = blockRow + rid;
        if (r < N_QUERY) {
            const float* src = q + (size_t)r * F_IN + kc + seg * 8;
            av[i][0] = *(const float4*)(src);
            av[i][1] = *(const float4*)(src + 4);
        } else if (r < N_QUERY + N_SUPPORT) {
            const float* src = s + (size_t)(r - N_QUERY) * F_IN + kc + seg * 8;
            av[i][0] = *(const float4*)(src);
            av[i][1] = *(const float4*)(src + 4);
        } else {
            av[i][0] = make_float4(0.f, 0.f, 0.f, 0.f);
            av[i][1] = make_float4(0.f, 0.f, 0.f, 0.f);
        }
    }
}

__device__ __forceinline__ void stsA(char* stagePtr, const float4 av[4][2], int tid)
{
    #pragma unroll
    for (int i = 0; i < 4; i++) {
        const int id  = tid + i * 256;
        const int rid = id >> 3;
        const int seg = id & 7;
        union { __half h[8]; uint4 u; } pk;
        const float* f = (const float*)&av[i][0];
        #pragma unroll
        for (int j = 0; j < 8; j++) pk.h[j] = __float2half_rn(f[j]);
        *(uint4*)(stagePtr + SA + rid * ROWB + seg * 16) = pk.u;
    }
}

__device__ __forceinline__ void copy_B(uint32_t sb, int blockCol, int c, int tid)
{
    const size_t kc = (size_t)c * GK;
    #pragma unroll
    for (int i = 0; i < 8; i++) {
        const int id  = tid + i * 256;
        const int rid = id >> 3;
        const int seg = id & 7;
        const char* src = (const char*)g_Wt
                        + ((size_t)(blockCol + rid) * F_IN + kc) * 2 + seg * 16;
        cp_async16(sb + SB + rid * ROWB + seg * 16, src);
    }
}

#define MMA_PASS(ACC, A, B)                                   \
    _Pragma("unroll")                                         \
    for (int mt = 0; mt < 4; mt++) {                          \
        _Pragma("unroll")                                     \
        for (int p = 0; p < 4; p++) {                         \
            mma_f16(ACC[mt][p * 2 + 0], A[mt], &B[p][0]);     \
            mma_f16(ACC[mt][p * 2 + 1], A[mt], &B[p][2]);     \
        }                                                     \
    }

__global__ __launch_bounds__(256, 1)
void gemm_fp16(const float* __restrict__ q, const float* __restrict__ s,
               const float* __restrict__ bias)
{
    extern __shared__ char smem[];
    const uint32_t sbase = smem_u32(smem);
    const int tid = threadIdx.x;
    const int wid = tid >> 5;
    const int l   = tid & 31;
    const int warpM = wid >> 2;          // 0..1 -> 64-row strip
    const int warpN = wid & 3;           // 0..3 -> 64-col strip
    const int blockRow = blockIdx.y * GM;
    const int blockCol = blockIdx.x * GN;

    const uint32_t aOff = (uint32_t)((warpM * 64 + (l & 15)) * ROWB + (l >> 4) * 16);
    uint32_t bOff[4];
    #pragma unroll
    for (int p = 0; p < 4; p++)
        bOff[p] = (uint32_t)(SB + (warpN * 64 + p * 16 + ((l >> 4) & 1) * 8 + (l & 7)) * ROWB
                             + ((l >> 3) & 1) * 16);

    float acc[4][8][4];
    #pragma unroll
    for (int mt = 0; mt < 4; mt++)
        #pragma unroll
        for (int nt = 0; nt < 8; nt++)
            #pragma unroll
            for (int r = 0; r < 4; r++) acc[mt][nt][r] = 0.f;

    // prologue
    {
        float4 av[4][2];
        ldgA(av, q, s, blockRow, 0, tid); stsA(smem, av, tid);
        ldgA(av, q, s, blockRow, 1, tid); stsA(smem + STAGE, av, tid);
    }
    copy_B(sbase, blockCol, 0, tid);
    cp_commit();
    copy_B(sbase + STAGE, blockCol, 1, tid);
    cp_commit();

    uint32_t stOff = 0;
    uint32_t wrOff = 2 * STAGE;

    for (int c = 0; c < NCH; c++) {
        const bool pf = (c + 2 < NCH);
        float4 av[4][2];
        if (pf) ldgA(av, q, s, blockRow, c + 2, tid);

        cp_wait1();
        __syncthreads();

        if (pf) copy_B(sbase + wrOff, blockCol, c + 2, tid);
        cp_commit();

        const uint32_t st = sbase + stOff;
        #pragma unroll
        for (int ks = 0; ks < 4; ks++) {
            const uint32_t kb = ks * 32;
            uint32_t aF[4][4], bF[4][4];

            #pragma unroll
            for (int mt = 0; mt < 4; mt++) ldmx4(aF[mt], st + aOff + mt * (16 * ROWB) + kb);
            #pragma unroll
            for (int p = 0; p < 4; p++)   ldmx4(bF[p], st + bOff[p] + kb);

            MMA_PASS(acc, aF, bF);
        }

        if (pf) stsA(smem + wrOff, av, tid);

        stOff += STAGE; if (stOff == NSTAGE * STAGE) stOff = 0;
        wrOff += STAGE; if (wrOff == NSTAGE * STAGE) wrOff = 0;
    }

    // epilogue: + bias; query rows -> fp16 g_Zh + row-stat partials;
    // support rows -> fp32 g_Z
    const bool isQuery = (blockRow < N_QUERY);
    const int  pidx    = blockIdx.x * 4 + warpN;   // 0..15
    #pragma unroll
    for (int mt = 0; mt < 4; mt++) {
        const int r0 = blockRow + warpM * 64 + mt * 16 + (l >> 2);
        float s0 = 0.f, t0 = 0.f, s8 = 0.f, t8 = 0.f;
        #pragma unroll
        for (int nt = 0; nt < 8; nt++) {
            const int col = blockCol + warpN * 64 + nt * 8 + (l & 3) * 2;
            const float b0 = bias[col], b1 = bias[col + 1];
            const float v00 = acc[mt][nt][0] + b0, v01 = acc[mt][nt][1] + b1;
            const float v10 = acc[mt][nt][2] + b0, v11 = acc[mt][nt][3] + b1;
            if (isQuery) {
                __half2 h0, h1;
                h0.x = __float2half_rn(v00); h0.y = __float2half_rn(v01);
                h1.x = __float2half_rn(v10); h1.y = __float2half_rn(v11);
                *(__half2*)(g_Zh + (size_t)r0 * D_EMB + col)       = h0;
                *(__half2*)(g_Zh + (size_t)(r0 + 8) * D_EMB + col) = h1;
                // stats from the quantized values (consistent with dist cross)
                const float f00 = __half2float(h0.x), f01 = __half2float(h0.y);
                const float f10 = __half2float(h1.x), f11 = __half2float(h1.y);
                s0 += f00 + f01; t0 += f00 * f00 + f01 * f01;
                s8 += f10 + f11; t8 += f10 * f10 + f11 * f11;
            } else {
                *(float2*)(g_Z + (size_t)r0 * D_EMB + col)       = make_float2(v00, v01);
                *(float2*)(g_Z + (size_t)(r0 + 8) * D_EMB + col) = make_float2(v10, v11);
            }
        }
        if (isQuery) {
            #pragma unroll
            for (int m = 1; m <= 2; m <<= 1) {
                s0 += __shfl_xor_sync(0xFFFFFFFFu, s0, m);
                t0 += __shfl_xor_sync(0xFFFFFFFFu, t0, m);
                s8 += __shfl_xor_sync(0xFFFFFFFFu, s8, m);
                t8 += __shfl_xor_sync(0xFFFFFFFFu, t8, m);
            }
            if ((l & 3) == 0) {
                g_qs_p[pidx][r0]     = s0;  g_q2_p[pidx][r0]     = t0;
                g_qs_p[pidx][r0 + 8] = s8;  g_q2_p[pidx][r0 + 8] = t8;
            }
        }
    }
}

// =====================================================================
// Kernel E: prototypes (one thread per dim, one block per class) +
// folded qstats final sum (first 8 blocks sum the 16 partials per row).
// =====================================================================
__global__ __launch_bounds__(1024)
void proto_kernel(const int* __restrict__ labels)
{
    const int c   = blockIdx.x;      // 0..127
    const int tid = threadIdx.x;     // 0..1023
    const int l   = tid & 31;

    // folded qstats: blocks 0..7 cover rows 0..8191
    {
        const int r = blockIdx.x * 1024 + tid;
        if (r < N_QUERY) {
            float s = 0.f, s2 = 0.f;
            #pragma unroll
            for (int p = 0; p < 16; p++) {
                s  += g_qs_p[p][r];
                s2 += g_q2_p[p][r];
            }
            g_qs[r] = s;
            g_q2[r] = s2;
        }
    }

    __shared__ float s_sum[1024], s_sum2[1024];
    __shared__ int   s_idx[K_SHOT];

    if (c < N_WAY && tid < 32) {
        int base = 0;
        for (int i0 = 0; i0 < N_SUPPORT; i0 += 32) {
            const int i = i0 + l;
            const bool match = (i < N_SUPPORT) && (labels[i] == c);
            const unsigned m = __ballot_sync(0xFFFFFFFFu, match);
            if (match) {
                const int pos = base + __popc(m & ((1u << l) - 1u));
                if (pos < K_SHOT) s_idx[pos] = i;
            }
            base += __popc(m);
        }
    }
    __syncthreads();

    float psum = 0.f, psum2 = 0.f;
    if (c < N_WAY) {
        float v[K_SHOT];
        #pragma unroll
        for (int j = 0; j < K_SHOT; j++)
            v[j] = g_Z[(size_t)(N_QUERY + s_idx[j]) * D_EMB + tid];

        float mean = 0.f;
        #pragma unroll
        for (int j = 0; j < K_SHOT; j++) mean += v[j];
        mean *= (1.0f / K_SHOT);

        #pragma unroll
        for (int p = 0; p < K_SHOT - 1; p++)
            #pragma unroll
            for (int qq = 0; qq < K_SHOT - 1 - p; qq++) {
                float lo = fminf(v[qq], v[qq + 1]);
                float hi = fmaxf(v[qq], v[qq + 1]);
                v[qq] = lo; v[qq + 1] = hi;
            }
        const float med = v[(K_SHOT - 1) / 2];
        const float zt  = 0.5f * (med + mean);
        g_Ph[(size_t)c * D_EMB + tid] = __float2half_rn(zt);
        psum = zt; psum2 = zt * zt;
    } else {
        g_Ph[(size_t)c * D_EMB + tid] = __float2half_rn(0.f);
    }

    s_sum[tid] = psum; s_sum2[tid] = psum2;
    __syncthreads();
    for (int st = 512; st > 0; st >>= 1) {
        if (tid < st) { s_sum[tid] += s_sum[tid + st]; s_sum2[tid] += s_sum2[tid + st]; }
        __syncthreads();
    }
    if (tid == 0 && c < N_WAY) { g_ps[c] = s_sum[0]; g_p2[c] = s_sum2[0]; }
}

// =====================================================================
// Kernel G: distance matrix — fp16 mma GEMM (64 x 128pad x 1024), 128
// CTAs for full chip fill, fused PairwiseDistance-eps epilogue.
// 8 warps, warp tile 16x64, 2-stage cp.async.
// =====================================================================
#define D2M 64
#define D2K 64
#define NCH2 (D_EMB / D2K)                  // 16
#define S2A 0
#define S2B (D2M * ROWB)                    // 9216
#define STAGE2 ((D2M + 128) * ROWB)         // 27648
#define DIST_SMEM (2 * STAGE2)              // 55296

__device__ __forceinline__ void copy_chunk2(uint32_t sb, int blockRow, int c, int tid)
{
    const size_t kb = (size_t)c * D2K * 2;
    #pragma unroll
    for (int i = 0; i < 2; i++) {            // A: 64 rows x 8 segs
        const int id = tid + i * 256, rid = id >> 3, seg = id & 7;
        cp_async16(sb + S2A + rid * ROWB + seg * 16,
                   (const char*)g_Zh + ((size_t)(blockRow + rid) * D_EMB) * 2 + kb + seg * 16);
    }
    #pragma unroll
    for (int i = 0; i < 4; i++) {            // B: 128 rows x 8 segs
        const int id = tid + i * 256, rid = id >> 3, seg = id & 7;
        cp_async16(sb + S2B + rid * ROWB + seg * 16,
                   (const char*)g_Ph + ((size_t)rid * D_EMB) * 2 + kb + seg * 16);
    }
}

__global__ __launch_bounds__(256, 1)
void dist_mma_kernel(float* __restrict__ out)
{
    extern __shared__ char smem[];
    const uint32_t sbase = smem_u32(smem);
    const int tid = threadIdx.x;
    const int wid = tid >> 5;
    const int l   = tid & 31;
    const int warpM = wid >> 1;          // 0..3 -> 16-row strip
    const int warpN = wid & 1;           // 0..1 -> 64-col strip
    const int blockRow = blockIdx.x * D2M;

    const uint32_t aOff = (uint32_t)((warpM * 16 + (l & 15)) * ROWB + (l >> 4) * 16);
    uint32_t bOff[4];
    #pragma unroll
    for (int p = 0; p < 4; p++)
        bOff[p] = (uint32_t)(S2B + (warpN * 64 + p * 16 + ((l >> 4) & 1) * 8 + (l & 7)) * ROWB
                             + ((l >> 3) & 1) * 16);

    float acc[8][4];
    #pragma unroll
    for (int nt = 0; nt < 8; nt++)
        #pragma unroll
        for (int r = 0; r < 4; r++) acc[nt][r] = 0.f;

    copy_chunk2(sbase, blockRow, 0, tid);
    cp_commit();

    for (int c = 0; c < NCH2; c++) {
        cp_wait0();
        __syncthreads();
        if (c + 1 < NCH2)
            copy_chunk2(sbase + (uint32_t)((c + 1) & 1) * STAGE2, blockRow, c + 1, tid);
        cp_commit();

        const uint32_t st = sbase + (uint32_t)(c & 1) * STAGE2;
        #pragma unroll
        for (int ks = 0; ks < 4; ks++) {
            const uint32_t kb = ks * 32;
            uint32_t aF[4], bF[4][4];

            ldmx4(aF, st + aOff + kb);
            #pragma unroll
            for (int p = 0; p < 4; p++)   ldmx4(bF[p], st + bOff[p] + kb);

            #pragma unroll
            for (int p = 0; p < 4; p++) {
                mma_f16(acc[p * 2 + 0], aF, &bF[p][0]);
                mma_f16(acc[p * 2 + 1], aF, &bF[p][2]);
            }
        }
        __syncthreads();
    }

    // fused distance epilogue
    const float deps2 = (float)D_EMB * EPS_F * EPS_F;
    {
        const int r0 = blockRow + warpM * 16 + (l >> 2);
        const float q2a = g_q2[r0],     qsa = g_qs[r0];
        const float q2b = g_q2[r0 + 8], qsb = g_qs[r0 + 8];
        #pragma unroll
        for (int nt = 0; nt < 8; nt++) {
            const int c0 = warpN * 64 + nt * 8 + (l & 3) * 2;
            #pragma unroll
            for (int jj = 0; jj < 2; jj++) {
                const int c = c0 + jj;
                if (c < N_WAY) {
                    const float p2v = g_p2[c], psv = g_ps[c];
                    float sqa = q2a + p2v - 2.0f * acc[nt][jj]
                              + 2.0f * EPS_F * (qsa - psv) + deps2;
                    float sqb = q2b + p2v - 2.0f * acc[nt][2 + jj]
                              + 2.0f * EPS_F * (qsb - psv) + deps2;
                    out[(size_t)r0 * N_WAY + c]       = -sqrtf(fmaxf(sqa, 0.0f));
                    out[(size_t)(r0 + 8) * N_WAY + c] = -sqrtf(fmaxf(sqb, 0.0f));
                }
            }
        }
    }
}

// =====================================================================
// launch
// =====================================================================
extern "C" void kernel_launch(void* const* d_in, const int* in_sizes, int n_in,
                              void* d_out, int out_size)
{
    const float* support = (const float*)d_in[0];
    const int*   labels  = (const int*)  d_in[1];
    const float* query   = (const float*)d_in[2];
    const float* W       = (const float*)d_in[3];
    const float* b       = (const float*)d_in[4];
    float*       out     = (float*)d_out;

    cudaFuncSetAttribute(gemm_fp16,
                         cudaFuncAttributeMaxDynamicSharedMemorySize, GEMM_SMEM);
    cudaFuncSetAttribute(dist_mma_kernel,
                         cudaFuncAttributeMaxDynamicSharedMemorySize, DIST_SMEM);

    convert_W<<<dim3(F_IN / 32, D_EMB / 32), dim3(32, 8)>>>(W);

    gemm_fp16<<<dim3(D_EMB / GN, M_TOT / GM), 256, GEMM_SMEM>>>(query, support, b);

    proto_kernel<<<128, 1024>>>(labels);
    dist_mma_kernel<<<N_QUERY / D2M, 256, DIST_SMEM>>>(out);
}

// round 16
// speedup vs baseline: 3.0167x; 1.0130x over previous
#include <cuda_runtime.h>
#include <cuda_fp16.h>
#include <math.h>
#include <stdint.h>

#define N_WAY     100
#define K_SHOT    10
#define N_SUPPORT 1000
#define N_QUERY   8192
#define F_IN      4096
#define D_EMB     1024
#define EPS_F     1e-6f

#define M_TOT     9216   // 8192 query rows + 1000 support + 24 pad

// ---------------- scratch (static device globals; no allocations) ----------
__device__ __half g_Wt[(size_t)D_EMB * F_IN];       // W transposed, fp16
__device__ float  g_Z[(size_t)M_TOT * D_EMB];       // fp32 embeddings (support rows)
__device__ __half g_Zh[(size_t)N_QUERY * D_EMB];    // fp16 query embeddings
__device__ __half g_Ph[128 * D_EMB];                // fp16 prototypes (pad 128)
__device__ float g_p2[128];
__device__ float g_ps[128];
__device__ float g_q2[N_QUERY];
__device__ float g_qs[N_QUERY];
__device__ float g_qs_p[16][N_QUERY];               // per-(Nblock,warpN) partial sums
__device__ float g_q2_p[16][N_QUERY];

// ======================= portable PTX helpers ==============================
__device__ __forceinline__ uint32_t smem_u32(const void* p) {
    uint32_t a;
    asm("{ .reg .u64 t; cvta.to.shared.u64 t, %1; cvt.u32.u64 %0, t; }"
        : "=r"(a) : "l"(p));
    return a;
}
__device__ __forceinline__ void cp_async16(uint32_t dst, const void* src) {
    asm volatile("cp.async.cg.shared.global [%0], [%1], 16;"
                 :: "r"(dst), "l"(src) : "memory");
}
__device__ __forceinline__ void cp_commit() {
    asm volatile("cp.async.commit_group;" ::: "memory");
}
__device__ __forceinline__ void cp_wait1() {
    asm volatile("cp.async.wait_group 1;" ::: "memory");
}
__device__ __forceinline__ void cp_wait2() {
    asm volatile("cp.async.wait_group 2;" ::: "memory");
}
__device__ __forceinline__ void ldmx4(uint32_t* r, uint32_t addr) {
    asm volatile("ldmatrix.sync.aligned.m8n8.x4.shared.b16 {%0,%1,%2,%3}, [%4];"
                 : "=r"(r[0]), "=r"(r[1]), "=r"(r[2]), "=r"(r[3]) : "r"(addr));
}
__device__ __forceinline__ void mma_f16(float* c, const uint32_t* a, const uint32_t* b) {
    asm volatile(
        "mma.sync.aligned.m16n8k16.row.col.f32.f16.f16.f32 "
        "{%0,%1,%2,%3}, {%4,%5,%6,%7}, {%8,%9}, {%0,%1,%2,%3};"
        : "+f"(c[0]), "+f"(c[1]), "+f"(c[2]), "+f"(c[3])
        : "r"(a[0]), "r"(a[1]), "r"(a[2]), "r"(a[3]), "r"(b[0]), "r"(b[1]));
}

// =====================================================================
// Kernel B: transpose W [4096,1024] -> Wt [1024,4096] fp16
// =====================================================================
__global__ void convert_W(const float* __restrict__ W)
{
    __shared__ __half th[32][33];
    const int k0 = blockIdx.x * 32, n0 = blockIdx.y * 32;
    const int tx = threadIdx.x, ty = threadIdx.y;   // (32, 8)
    #pragma unroll
    for (int i = 0; i < 4; i++) {
        const int kk = ty + i * 8;
        th[kk][tx] = __float2half_rn(W[(size_t)(k0 + kk) * D_EMB + n0 + tx]);
    }
    __syncthreads();
    #pragma unroll
    for (int i = 0; i < 4; i++) {
        const int nn = ty + i * 8;
        g_Wt[(size_t)(n0 + nn) * F_IN + k0 + tx] = th[tx][nn];
    }
}

// =====================================================================
// Kernel C: single-pass fp16 GEMM with fused A conversion AND fused
// per-row sum/sum-of-squares partials for query rows.
// =====================================================================
#define GM 128
#define GN 256
#define GK 64
#define NCH (F_IN / GK)          // 64
#define ROWB 144                 // 64 fp16 (128B) + 16B pad
#define SA    0
#define SB    (GM * ROWB)                      // 18432
#define STAGE (GM * ROWB + GN * ROWB)          // 55296
#define NSTAGE 3
#define GEMM_SMEM (NSTAGE * STAGE)             // 165888

__device__ __forceinline__ void ldgA(float4 av[4][2],
                                     const float* __restrict__ q,
                                     const float* __restrict__ s,
                                     int blockRow, int c, int tid)
{
    const int kc = c * GK;
    #pragma unroll
    for (int i = 0; i < 4; i++) {
        const int id  = tid + i * 256;
        const int rid = id >> 3;
        const int seg = id & 7;
        const int r   = blockRow + rid;
        if (r < N_QUERY) {
            const float* src = q + (size_t)r * F_IN + kc + seg * 8;
            av[i][0] = *(const float4*)(src);
            av[i][1] = *(const float4*)(src + 4);
        } else if (r < N_QUERY + N_SUPPORT) {
            const float* src = s + (size_t)(r - N_QUERY) * F_IN + kc + seg * 8;
            av[i][0] = *(const float4*)(src);
            av[i][1] = *(const float4*)(src + 4);
        } else {
            av[i][0] = make_float4(0.f, 0.f, 0.f, 0.f);
            av[i][1] = make_float4(0.f, 0.f, 0.f, 0.f);
        }
    }
}

__device__ __forceinline__ void stsA(char* stagePtr, const float4 av[4][2], int tid)
{
    #pragma unroll
    for (int i = 0; i < 4; i++) {
        const int id  = tid + i * 256;
        const int rid = id >> 3;
        const int seg = id & 7;
        union { __half h[8]; uint4 u; } pk;
        const float* f = (const float*)&av[i][0];
        #pragma unroll
        for (int j = 0; j < 8; j++) pk.h[j] = __float2half_rn(f[j]);
        *(uint4*)(stagePtr + SA + rid * ROWB + seg * 16) = pk.u;
    }
}

__device__ __forceinline__ void copy_B(uint32_t sb, int blockCol, int c, int tid)
{
    const size_t kc = (size_t)c * GK;
    #pragma unroll
    for (int i = 0; i < 8; i++) {
        const int id  = tid + i * 256;
        const int rid = id >> 3;
        const int seg = id & 7;
        const char* src = (const char*)g_Wt
                        + ((size_t)(blockCol + rid) * F_IN + kc) * 2 + seg * 16;
        cp_async16(sb + SB + rid * ROWB + seg * 16, src);
    }
}

#define MMA_PASS(ACC, A, B)                                   \
    _Pragma("unroll")                                         \
    for (int mt = 0; mt < 4; mt++) {                          \
        _Pragma("unroll")                                     \
        for (int p = 0; p < 4; p++) {                         \
            mma_f16(ACC[mt][p * 2 + 0], A[mt], &B[p][0]);     \
            mma_f16(ACC[mt][p * 2 + 1], A[mt], &B[p][2]);     \
        }                                                     \
    }

__global__ __launch_bounds__(256, 1)
void gemm_fp16(const float* __restrict__ q, const float* __restrict__ s,
               const float* __restrict__ bias)
{
    extern __shared__ char smem[];
    const uint32_t sbase = smem_u32(smem);
    const int tid = threadIdx.x;
    const int wid = tid >> 5;
    const int l   = tid & 31;
    const int warpM = wid >> 2;          // 0..1 -> 64-row strip
    const int warpN = wid & 3;           // 0..3 -> 64-col strip
    const int blockRow = blockIdx.y * GM;
    const int blockCol = blockIdx.x * GN;

    const uint32_t aOff = (uint32_t)((warpM * 64 + (l & 15)) * ROWB + (l >> 4) * 16);
    uint32_t bOff[4];
    #pragma unroll
    for (int p = 0; p < 4; p++)
        bOff[p] = (uint32_t)(SB + (warpN * 64 + p * 16 + ((l >> 4) & 1) * 8 + (l & 7)) * ROWB
                             + ((l >> 3) & 1) * 16);

    float acc[4][8][4];
    #pragma unroll
    for (int mt = 0; mt < 4; mt++)
        #pragma unroll
        for (int nt = 0; nt < 8; nt++)
            #pragma unroll
            for (int r = 0; r < 4; r++) acc[mt][nt][r] = 0.f;

    // prologue
    {
        float4 av[4][2];
        ldgA(av, q, s, blockRow, 0, tid); stsA(smem, av, tid);
        ldgA(av, q, s, blockRow, 1, tid); stsA(smem + STAGE, av, tid);
    }
    copy_B(sbase, blockCol, 0, tid);
    cp_commit();
    copy_B(sbase + STAGE, blockCol, 1, tid);
    cp_commit();

    uint32_t stOff = 0;
    uint32_t wrOff = 2 * STAGE;

    for (int c = 0; c < NCH; c++) {
        const bool pf = (c + 2 < NCH);
        float4 av[4][2];
        if (pf) ldgA(av, q, s, blockRow, c + 2, tid);

        cp_wait1();
        __syncthreads();

        if (pf) copy_B(sbase + wrOff, blockCol, c + 2, tid);
        cp_commit();

        const uint32_t st = sbase + stOff;
        #pragma unroll
        for (int ks = 0; ks < 4; ks++) {
            const uint32_t kb = ks * 32;
            uint32_t aF[4][4], bF[4][4];

            #pragma unroll
            for (int mt = 0; mt < 4; mt++) ldmx4(aF[mt], st + aOff + mt * (16 * ROWB) + kb);
            #pragma unroll
            for (int p = 0; p < 4; p++)   ldmx4(bF[p], st + bOff[p] + kb);

            MMA_PASS(acc, aF, bF);
        }

        if (pf) stsA(smem + wrOff, av, tid);

        stOff += STAGE; if (stOff == NSTAGE * STAGE) stOff = 0;
        wrOff += STAGE; if (wrOff == NSTAGE * STAGE) wrOff = 0;
    }

    // epilogue: + bias; query rows -> fp16 g_Zh + row-stat partials;
    // support rows -> fp32 g_Z
    const bool isQuery = (blockRow < N_QUERY);
    const int  pidx    = blockIdx.x * 4 + warpN;   // 0..15
    #pragma unroll
    for (int mt = 0; mt < 4; mt++) {
        const int r0 = blockRow + warpM * 64 + mt * 16 + (l >> 2);
        float s0 = 0.f, t0 = 0.f, s8 = 0.f, t8 = 0.f;
        #pragma unroll
        for (int nt = 0; nt < 8; nt++) {
            const int col = blockCol + warpN * 64 + nt * 8 + (l & 3) * 2;
            const float b0 = bias[col], b1 = bias[col + 1];
            const float v00 = acc[mt][nt][0] + b0, v01 = acc[mt][nt][1] + b1;
            const float v10 = acc[mt][nt][2] + b0, v11 = acc[mt][nt][3] + b1;
            if (isQuery) {
                __half2 h0, h1;
                h0.x = __float2half_rn(v00); h0.y = __float2half_rn(v01);
                h1.x = __float2half_rn(v10); h1.y = __float2half_rn(v11);
                *(__half2*)(g_Zh + (size_t)r0 * D_EMB + col)       = h0;
                *(__half2*)(g_Zh + (size_t)(r0 + 8) * D_EMB + col) = h1;
                const float f00 = __half2float(h0.x), f01 = __half2float(h0.y);
                const float f10 = __half2float(h1.x), f11 = __half2float(h1.y);
                s0 += f00 + f01; t0 += f00 * f00 + f01 * f01;
                s8 += f10 + f11; t8 += f10 * f10 + f11 * f11;
            } else {
                *(float2*)(g_Z + (size_t)r0 * D_EMB + col)       = make_float2(v00, v01);
                *(float2*)(g_Z + (size_t)(r0 + 8) * D_EMB + col) = make_float2(v10, v11);
            }
        }
        if (isQuery) {
            #pragma unroll
            for (int m = 1; m <= 2; m <<= 1) {
                s0 += __shfl_xor_sync(0xFFFFFFFFu, s0, m);
                t0 += __shfl_xor_sync(0xFFFFFFFFu, t0, m);
                s8 += __shfl_xor_sync(0xFFFFFFFFu, s8, m);
                t8 += __shfl_xor_sync(0xFFFFFFFFu, t8, m);
            }
            if ((l & 3) == 0) {
                g_qs_p[pidx][r0]     = s0;  g_q2_p[pidx][r0]     = t0;
                g_qs_p[pidx][r0 + 8] = s8;  g_q2_p[pidx][r0 + 8] = t8;
            }
        }
    }
}

// =====================================================================
// Kernel E: prototypes (one thread per dim, one block per class) +
// folded qstats final sum (first 8 blocks sum the 16 partials per row).
// =====================================================================
__global__ __launch_bounds__(1024)
void proto_kernel(const int* __restrict__ labels)
{
    const int c   = blockIdx.x;      // 0..127
    const int tid = threadIdx.x;     // 0..1023
    const int l   = tid & 31;

    // folded qstats: blocks 0..7 cover rows 0..8191
    {
        const int r = blockIdx.x * 1024 + tid;
        if (r < N_QUERY) {
            float s = 0.f, s2 = 0.f;
            #pragma unroll
            for (int p = 0; p < 16; p++) {
                s  += g_qs_p[p][r];
                s2 += g_q2_p[p][r];
            }
            g_qs[r] = s;
            g_q2[r] = s2;
        }
    }

    __shared__ float s_sum[1024], s_sum2[1024];
    __shared__ int   s_idx[K_SHOT];

    if (c < N_WAY && tid < 32) {
        int base = 0;
        for (int i0 = 0; i0 < N_SUPPORT; i0 += 32) {
            const int i = i0 + l;
            const bool match = (i < N_SUPPORT) && (labels[i] == c);
            const unsigned m = __ballot_sync(0xFFFFFFFFu, match);
            if (match) {
                const int pos = base + __popc(m & ((1u << l) - 1u));
                if (pos < K_SHOT) s_idx[pos] = i;
            }
            base += __popc(m);
        }
    }
    __syncthreads();

    float psum = 0.f, psum2 = 0.f;
    if (c < N_WAY) {
        float v[K_SHOT];
        #pragma unroll
        for (int j = 0; j < K_SHOT; j++)
            v[j] = g_Z[(size_t)(N_QUERY + s_idx[j]) * D_EMB + tid];

        float mean = 0.f;
        #pragma unroll
        for (int j = 0; j < K_SHOT; j++) mean += v[j];
        mean *= (1.0f / K_SHOT);

        #pragma unroll
        for (int p = 0; p < K_SHOT - 1; p++)
            #pragma unroll
            for (int qq = 0; qq < K_SHOT - 1 - p; qq++) {
                float lo = fminf(v[qq], v[qq + 1]);
                float hi = fmaxf(v[qq], v[qq + 1]);
                v[qq] = lo; v[qq + 1] = hi;
            }
        const float med = v[(K_SHOT - 1) / 2];
        const float zt  = 0.5f * (med + mean);
        g_Ph[(size_t)c * D_EMB + tid] = __float2half_rn(zt);
        psum = zt; psum2 = zt * zt;
    } else {
        g_Ph[(size_t)c * D_EMB + tid] = __float2half_rn(0.f);
    }

    s_sum[tid] = psum; s_sum2[tid] = psum2;
    __syncthreads();
    for (int st = 512; st > 0; st >>= 1) {
        if (tid < st) { s_sum[tid] += s_sum[tid + st]; s_sum2[tid] += s_sum2[tid + st]; }
        __syncthreads();
    }
    if (tid == 0 && c < N_WAY) { g_ps[c] = s_sum[0]; g_p2[c] = s_sum2[0]; }
}

// =====================================================================
// Kernel G: distance matrix — fp16 mma GEMM (64 x 128pad x 1024), 128
// CTAs, 4-STAGE cp.async pipeline (3 chunks in flight) to hide the
// per-chunk DRAM/L2 latency exposed by the small tile.
// =====================================================================
#define D2M 64
#define D2K 64
#define NCH2 (D_EMB / D2K)                  // 16
#define S2A 0
#define S2B (D2M * ROWB)                    // 9216
#define STAGE2 ((D2M + 128) * ROWB)         // 27648
#define NSTAGE2 4
#define DIST_SMEM (NSTAGE2 * STAGE2)        // 110592

__device__ __forceinline__ void copy_chunk2(uint32_t sb, int blockRow, int c, int tid)
{
    const size_t kb = (size_t)c * D2K * 2;
    #pragma unroll
    for (int i = 0; i < 2; i++) {            // A: 64 rows x 8 segs
        const int id = tid + i * 256, rid = id >> 3, seg = id & 7;
        cp_async16(sb + S2A + rid * ROWB + seg * 16,
                   (const char*)g_Zh + ((size_t)(blockRow + rid) * D_EMB) * 2 + kb + seg * 16);
    }
    #pragma unroll
    for (int i = 0; i < 4; i++) {            // B: 128 rows x 8 segs
        const int id = tid + i * 256, rid = id >> 3, seg = id & 7;
        cp_async16(sb + S2B + rid * ROWB + seg * 16,
                   (const char*)g_Ph + ((size_t)rid * D_EMB) * 2 + kb + seg * 16);
    }
}

__global__ __launch_bounds__(256, 1)
void dist_mma_kernel(float* __restrict__ out)
{
    extern __shared__ char smem[];
    const uint32_t sbase = smem_u32(smem);
    const int tid = threadIdx.x;
    const int wid = tid >> 5;
    const int l   = tid & 31;
    const int warpM = wid >> 1;          // 0..3 -> 16-row strip
    const int warpN = wid & 1;           // 0..1 -> 64-col strip
    const int blockRow = blockIdx.x * D2M;

    const uint32_t aOff = (uint32_t)((warpM * 16 + (l & 15)) * ROWB + (l >> 4) * 16);
    uint32_t bOff[4];
    #pragma unroll
    for (int p = 0; p < 4; p++)
        bOff[p] = (uint32_t)(S2B + (warpN * 64 + p * 16 + ((l >> 4) & 1) * 8 + (l & 7)) * ROWB
                             + ((l >> 3) & 1) * 16);

    float acc[8][4];
    #pragma unroll
    for (int nt = 0; nt < 8; nt++)
        #pragma unroll
        for (int r = 0; r < 4; r++) acc[nt][r] = 0.f;

    // prologue: 3 chunks in flight
    copy_chunk2(sbase, blockRow, 0, tid);              cp_commit();
    copy_chunk2(sbase + STAGE2, blockRow, 1, tid);     cp_commit();
    copy_chunk2(sbase + 2 * STAGE2, blockRow, 2, tid); cp_commit();

    uint32_t stOff = 0;
    uint32_t wrOff = 3 * STAGE2;

    for (int c = 0; c < NCH2; c++) {
        cp_wait2();            // chunk c resident (<=2 groups outstanding)
        __syncthreads();       // compute c-1 done everywhere -> stage wrOff free

        if (c + 3 < NCH2) copy_chunk2(sbase + wrOff, blockRow, c + 3, tid);
        cp_commit();

        const uint32_t st = sbase + stOff;
        #pragma unroll
        for (int ks = 0; ks < 4; ks++) {
            const uint32_t kb = ks * 32;
            uint32_t aF[4], bF[4][4];

            ldmx4(aF, st + aOff + kb);
            #pragma unroll
            for (int p = 0; p < 4; p++)   ldmx4(bF[p], st + bOff[p] + kb);

            #pragma unroll
            for (int p = 0; p < 4; p++) {
                mma_f16(acc[p * 2 + 0], aF, &bF[p][0]);
                mma_f16(acc[p * 2 + 1], aF, &bF[p][2]);
            }
        }

        stOff += STAGE2; if (stOff == NSTAGE2 * STAGE2) stOff = 0;
        wrOff += STAGE2; if (wrOff == NSTAGE2 * STAGE2) wrOff = 0;
    }

    // fused distance epilogue
    const float deps2 = (float)D_EMB * EPS_F * EPS_F;
    {
        const int r0 = blockRow + warpM * 16 + (l >> 2);
        const float q2a = g_q2[r0],     qsa = g_qs[r0];
        const float q2b = g_q2[r0 + 8], qsb = g_qs[r0 + 8];
        #pragma unroll
        for (int nt = 0; nt < 8; nt++) {
            const int c0 = warpN * 64 + nt * 8 + (l & 3) * 2;
            #pragma unroll
            for (int jj = 0; jj < 2; jj++) {
                const int c = c0 + jj;
                if (c < N_WAY) {
                    const float p2v = g_p2[c], psv = g_ps[c];
                    float sqa = q2a + p2v - 2.0f * acc[nt][jj]
                              + 2.0f * EPS_F * (qsa - psv) + deps2;
                    float sqb = q2b + p2v - 2.0f * acc[nt][2 + jj]
                              + 2.0f * EPS_F * (qsb - psv) + deps2;
                    out[(size_t)r0 * N_WAY + c]       = -sqrtf(fmaxf(sqa, 0.0f));
                    out[(size_t)(r0 + 8) * N_WAY + c] = -sqrtf(fmaxf(sqb, 0.0f));
                }
            }
        }
    }
}

// =====================================================================
// launch
// =====================================================================
extern "C" void kernel_launch(void* const* d_in, const int* in_sizes, int n_in,
                              void* d_out, int out_size)
{
    const float* support = (const float*)d_in[0];
    const int*   labels  = (const int*)  d_in[1];
    const float* query   = (const float*)d_in[2];
    const float* W       = (const float*)d_in[3];
    const float* b       = (const float*)d_in[4];
    float*       out     = (float*)d_out;

    cudaFuncSetAttribute(gemm_fp16,
                         cudaFuncAttributeMaxDynamicSharedMemorySize, GEMM_SMEM);
    cudaFuncSetAttribute(dist_mma_kernel,
                         cudaFuncAttributeMaxDynamicSharedMemorySize, DIST_SMEM);

    convert_W<<<dim3(F_IN / 32, D_EMB / 32), dim3(32, 8)>>>(W);

    gemm_fp16<<<dim3(D_EMB / GN, M_TOT / GM), 256, GEMM_SMEM>>>(query, support, b);

    proto_kernel<<<128, 1024>>>(labels);
    dist_mma_kernel<<<N_QUERY / D2M, 256, DIST_SMEM>>>(out);
}

// round 17
// speedup vs baseline: 3.0219x; 1.0017x over previous
#include <cuda_runtime.h>
#include <cuda_fp16.h>
#include <math.h>
#include <stdint.h>

#define N_WAY     100
#define K_SHOT    10
#define N_SUPPORT 1000
#define N_QUERY   8192
#define F_IN      4096
#define D_EMB     1024
#define EPS_F     1e-6f

#define M_TOT     9216   // 8192 query rows + 1000 support + 24 pad

// ---------------- scratch (static device globals; no allocations) ----------
__device__ __half g_Wt[(size_t)D_EMB * F_IN];       // W transposed, fp16
__device__ float  g_Z[(size_t)M_TOT * D_EMB];       // fp32 embeddings (support rows)
__device__ __half g_Zh[(size_t)N_QUERY * D_EMB];    // fp16 query embeddings
__device__ __half g_Ph[128 * D_EMB];                // fp16 prototypes (pad 128)
__device__ float g_p2[128];
__device__ float g_ps[128];
__device__ float g_q2[N_QUERY];
__device__ float g_qs[N_QUERY];
__device__ float g_qs_p[16][N_QUERY];               // per-(Nblock,warpN) partial sums
__device__ float g_q2_p[16][N_QUERY];

// ======================= portable PTX helpers ==============================
__device__ __forceinline__ uint32_t smem_u32(const void* p) {
    uint32_t a;
    asm("{ .reg .u64 t; cvta.to.shared.u64 t, %1; cvt.u32.u64 %0, t; }"
        : "=r"(a) : "l"(p));
    return a;
}
__device__ __forceinline__ void cp_async16(uint32_t dst, const void* src) {
    asm volatile("cp.async.cg.shared.global [%0], [%1], 16;"
                 :: "r"(dst), "l"(src) : "memory");
}
__device__ __forceinline__ void cp_commit() {
    asm volatile("cp.async.commit_group;" ::: "memory");
}
__device__ __forceinline__ void cp_wait1() {
    asm volatile("cp.async.wait_group 1;" ::: "memory");
}
__device__ __forceinline__ void ldmx4(uint32_t* r, uint32_t addr) {
    asm volatile("ldmatrix.sync.aligned.m8n8.x4.shared.b16 {%0,%1,%2,%3}, [%4];"
                 : "=r"(r[0]), "=r"(r[1]), "=r"(r[2]), "=r"(r[3]) : "r"(addr));
}
__device__ __forceinline__ void mma_f16(float* c, const uint32_t* a, const uint32_t* b) {
    asm volatile(
        "mma.sync.aligned.m16n8k16.row.col.f32.f16.f16.f32 "
        "{%0,%1,%2,%3}, {%4,%5,%6,%7}, {%8,%9}, {%0,%1,%2,%3};"
        : "+f"(c[0]), "+f"(c[1]), "+f"(c[2]), "+f"(c[3])
        : "r"(a[0]), "r"(a[1]), "r"(a[2]), "r"(a[3]), "r"(b[0]), "r"(b[1]));
}

// =====================================================================
// Kernel B: transpose W [4096,1024] -> Wt [1024,4096] fp16
// =====================================================================
__global__ void convert_W(const float* __restrict__ W)
{
    __shared__ __half th[32][33];
    const int k0 = blockIdx.x * 32, n0 = blockIdx.y * 32;
    const int tx = threadIdx.x, ty = threadIdx.y;   // (32, 8)
    #pragma unroll
    for (int i = 0; i < 4; i++) {
        const int kk = ty + i * 8;
        th[kk][tx] = __float2half_rn(W[(size_t)(k0 + kk) * D_EMB + n0 + tx]);
    }
    __syncthreads();
    #pragma unroll
    for (int i = 0; i < 4; i++) {
        const int nn = ty + i * 8;
        g_Wt[(size_t)(n0 + nn) * F_IN + k0 + tx] = th[tx][nn];
    }
}

// =====================================================================
// Kernel C: single-pass fp16 GEMM with fused A conversion AND fused
// per-row sum/sum-of-squares partials for query rows.
// =====================================================================
#define GM 128
#define GN 256
#define GK 64
#define NCH (F_IN / GK)          // 64
#define ROWB 144                 // 64 fp16 (128B) + 16B pad
#define SA    0
#define SB    (GM * ROWB)                      // 18432
#define STAGE (GM * ROWB + GN * ROWB)          // 55296
#define NSTAGE 3
#define GEMM_SMEM (NSTAGE * STAGE)             // 165888

__device__ __forceinline__ void ldgA(float4 av[4][2],
                                     const float* __restrict__ q,
                                     const float* __restrict__ s,
                                     int blockRow, int c, int tid)
{
    const int kc = c * GK;
    #pragma unroll
    for (int i = 0; i < 4; i++) {
        const int id  = tid + i * 256;
        const int rid = id >> 3;
        const int seg = id & 7;
        const int r   = blockRow + rid;
        if (r < N_QUERY) {
            const float* src = q + (size_t)r * F_IN + kc + seg * 8;
            av[i][0] = *(const float4*)(src);
            av[i][1] = *(const float4*)(src + 4);
        } else if (r < N_QUERY + N_SUPPORT) {
            const float* src = s + (size_t)(r - N_QUERY) * F_IN + kc + seg * 8;
            av[i][0] = *(const float4*)(src);
            av[i][1] = *(const float4*)(src + 4);
        } else {
            av[i][0] = make_float4(0.f, 0.f, 0.f, 0.f);
            av[i][1] = make_float4(0.f, 0.f, 0.f, 0.f);
        }
    }
}

__device__ __forceinline__ void stsA(char* stagePtr, const float4 av[4][2], int tid)
{
    #pragma unroll
    for (int i = 0; i < 4; i++) {
        const int id  = tid + i * 256;
        const int rid = id >> 3;
        const int seg = id & 7;
        union { __half h[8]; uint4 u; } pk;
        const float* f = (const float*)&av[i][0];
        #pragma unroll
        for (int j = 0; j < 8; j++) pk.h[j] = __float2half_rn(f[j]);
        *(uint4*)(stagePtr + SA + rid * ROWB + seg * 16) = pk.u;
    }
}

__device__ __forceinline__ void copy_B(uint32_t sb, int blockCol, int c, int tid)
{
    const size_t kc = (size_t)c * GK;
    #pragma unroll
    for (int i = 0; i < 8; i++) {
        const int id  = tid + i * 256;
        const int rid = id >> 3;
        const int seg = id & 7;
        const char* src = (const char*)g_Wt
                        + ((size_t)(blockCol + rid) * F_IN + kc) * 2 + seg * 16;
        cp_async16(sb + SB + rid * ROWB + seg * 16, src);
    }
}

#define MMA_PASS(ACC, A, B)                                   \
    _Pragma("unroll")                                         \
    for (int mt = 0; mt < 4; mt++) {                          \
        _Pragma("unroll")                                     \
        for (int p = 0; p < 4; p++) {                         \
            mma_f16(ACC[mt][p * 2 + 0], A[mt], &B[p][0]);     \
            mma_f16(ACC[mt][p * 2 + 1], A[mt], &B[p][2]);     \
        }                                                     \
    }

__global__ __launch_bounds__(256, 1)
void gemm_fp16(const float* __restrict__ q, const float* __restrict__ s,
               const float* __restrict__ bias)
{
    extern __shared__ char smem[];
    const uint32_t sbase = smem_u32(smem);
    const int tid = threadIdx.x;
    const int wid = tid >> 5;
    const int l   = tid & 31;
    const int warpM = wid >> 2;          // 0..1 -> 64-row strip
    const int warpN = wid & 3;           // 0..3 -> 64-col strip
    const int blockRow = blockIdx.y * GM;
    const int blockCol = blockIdx.x * GN;

    const uint32_t aOff = (uint32_t)((warpM * 64 + (l & 15)) * ROWB + (l >> 4) * 16);
    uint32_t bOff[4];
    #pragma unroll
    for (int p = 0; p < 4; p++)
        bOff[p] = (uint32_t)(SB + (warpN * 64 + p * 16 + ((l >> 4) & 1) * 8 + (l & 7)) * ROWB
                             + ((l >> 3) & 1) * 16);

    float acc[4][8][4];
    #pragma unroll
    for (int mt = 0; mt < 4; mt++)
        #pragma unroll
        for (int nt = 0; nt < 8; nt++)
            #pragma unroll
            for (int r = 0; r < 4; r++) acc[mt][nt][r] = 0.f;

    // prologue
    {
        float4 av[4][2];
        ldgA(av, q, s, blockRow, 0, tid); stsA(smem, av, tid);
        ldgA(av, q, s, blockRow, 1, tid); stsA(smem + STAGE, av, tid);
    }
    copy_B(sbase, blockCol, 0, tid);
    cp_commit();
    copy_B(sbase + STAGE, blockCol, 1, tid);
    cp_commit();

    uint32_t stOff = 0;
    uint32_t wrOff = 2 * STAGE;

    for (int c = 0; c < NCH; c++) {
        const bool pf = (c + 2 < NCH);
        float4 av[4][2];
        if (pf) ldgA(av, q, s, blockRow, c + 2, tid);

        cp_wait1();
        __syncthreads();

        if (pf) copy_B(sbase + wrOff, blockCol, c + 2, tid);
        cp_commit();

        const uint32_t st = sbase + stOff;
        #pragma unroll
        for (int ks = 0; ks < 4; ks++) {
            const uint32_t kb = ks * 32;
            uint32_t aF[4][4], bF[4][4];

            #pragma unroll
            for (int mt = 0; mt < 4; mt++) ldmx4(aF[mt], st + aOff + mt * (16 * ROWB) + kb);
            #pragma unroll
            for (int p = 0; p < 4; p++)   ldmx4(bF[p], st + bOff[p] + kb);

            MMA_PASS(acc, aF, bF);
        }

        if (pf) stsA(smem + wrOff, av, tid);

        stOff += STAGE; if (stOff == NSTAGE * STAGE) stOff = 0;
        wrOff += STAGE; if (wrOff == NSTAGE * STAGE) wrOff = 0;
    }

    // epilogue: + bias; query rows -> fp16 g_Zh + row-stat partials;
    // support rows -> fp32 g_Z
    const bool isQuery = (blockRow < N_QUERY);
    const int  pidx    = blockIdx.x * 4 + warpN;   // 0..15
    #pragma unroll
    for (int mt = 0; mt < 4; mt++) {
        const int r0 = blockRow + warpM * 64 + mt * 16 + (l >> 2);
        float s0 = 0.f, t0 = 0.f, s8 = 0.f, t8 = 0.f;
        #pragma unroll
        for (int nt = 0; nt < 8; nt++) {
            const int col = blockCol + warpN * 64 + nt * 8 + (l & 3) * 2;
            const float b0 = bias[col], b1 = bias[col + 1];
            const float v00 = acc[mt][nt][0] + b0, v01 = acc[mt][nt][1] + b1;
            const float v10 = acc[mt][nt][2] + b0, v11 = acc[mt][nt][3] + b1;
            if (isQuery) {
                __half2 h0, h1;
                h0.x = __float2half_rn(v00); h0.y = __float2half_rn(v01);
                h1.x = __float2half_rn(v10); h1.y = __float2half_rn(v11);
                *(__half2*)(g_Zh + (size_t)r0 * D_EMB + col)       = h0;
                *(__half2*)(g_Zh + (size_t)(r0 + 8) * D_EMB + col) = h1;
                const float f00 = __half2float(h0.x), f01 = __half2float(h0.y);
                const float f10 = __half2float(h1.x), f11 = __half2float(h1.y);
                s0 += f00 + f01; t0 += f00 * f00 + f01 * f01;
                s8 += f10 + f11; t8 += f10 * f10 + f11 * f11;
            } else {
                *(float2*)(g_Z + (size_t)r0 * D_EMB + col)       = make_float2(v00, v01);
                *(float2*)(g_Z + (size_t)(r0 + 8) * D_EMB + col) = make_float2(v10, v11);
            }
        }
        if (isQuery) {
            #pragma unroll
            for (int m = 1; m <= 2; m <<= 1) {
                s0 += __shfl_xor_sync(0xFFFFFFFFu, s0, m);
                t0 += __shfl_xor_sync(0xFFFFFFFFu, t0, m);
                s8 += __shfl_xor_sync(0xFFFFFFFFu, s8, m);
                t8 += __shfl_xor_sync(0xFFFFFFFFu, t8, m);
            }
            if ((l & 3) == 0) {
                g_qs_p[pidx][r0]     = s0;  g_q2_p[pidx][r0]     = t0;
                g_qs_p[pidx][r0 + 8] = s8;  g_q2_p[pidx][r0 + 8] = t8;
            }
        }
    }
}

// =====================================================================
// Kernel E: prototypes (one thread per dim, one block per class) +
// folded qstats final sum (first 8 blocks sum the 16 partials per row).
// =====================================================================
__global__ __launch_bounds__(1024)
void proto_kernel(const int* __restrict__ labels)
{
    const int c   = blockIdx.x;      // 0..127
    const int tid = threadIdx.x;     // 0..1023
    const int l   = tid & 31;

    // folded qstats: blocks 0..7 cover rows 0..8191
    {
        const int r = blockIdx.x * 1024 + tid;
        if (r < N_QUERY) {
            float s = 0.f, s2 = 0.f;
            #pragma unroll
            for (int p = 0; p < 16; p++) {
                s  += g_qs_p[p][r];
                s2 += g_q2_p[p][r];
            }
            g_qs[r] = s;
            g_q2[r] = s2;
        }
    }

    __shared__ float s_sum[1024], s_sum2[1024];
    __shared__ int   s_idx[K_SHOT];

    if (c < N_WAY && tid < 32) {
        int base = 0;
        for (int i0 = 0; i0 < N_SUPPORT; i0 += 32) {
            const int i = i0 + l;
            const bool match = (i < N_SUPPORT) && (labels[i] == c);
            const unsigned m = __ballot_sync(0xFFFFFFFFu, match);
            if (match) {
                const int pos = base + __popc(m & ((1u << l) - 1u));
                if (pos < K_SHOT) s_idx[pos] = i;
            }
            base += __popc(m);
        }
    }
    __syncthreads();

    float psum = 0.f, psum2 = 0.f;
    if (c < N_WAY) {
        float v[K_SHOT];
        #pragma unroll
        for (int j = 0; j < K_SHOT; j++)
            v[j] = g_Z[(size_t)(N_QUERY + s_idx[j]) * D_EMB + tid];

        float mean = 0.f;
        #pragma unroll
        for (int j = 0; j < K_SHOT; j++) mean += v[j];
        mean *= (1.0f / K_SHOT);

        #pragma unroll
        for (int p = 0; p < K_SHOT - 1; p++)
            #pragma unroll
            for (int qq = 0; qq < K_SHOT - 1 - p; qq++) {
                float lo = fminf(v[qq], v[qq + 1]);
                float hi = fmaxf(v[qq], v[qq + 1]);
                v[qq] = lo; v[qq + 1] = hi;
            }
        const float med = v[(K_SHOT - 1) / 2];
        const float zt  = 0.5f * (med + mean);
        g_Ph[(size_t)c * D_EMB + tid] = __float2half_rn(zt);
        psum = zt; psum2 = zt * zt;
    } else {
        g_Ph[(size_t)c * D_EMB + tid] = __float2half_rn(0.f);
    }

    s_sum[tid] = psum; s_sum2[tid] = psum2;
    __syncthreads();
    for (int st = 512; st > 0; st >>= 1) {
        if (tid < st) { s_sum[tid] += s_sum[tid + st]; s_sum2[tid] += s_sum2[tid + st]; }
        __syncthreads();
    }
    if (tid == 0 && c < N_WAY) { g_ps[c] = s_sum[0]; g_p2[c] = s_sum2[0]; }
}

// =====================================================================
// Kernel G: distance matrix — fp16 mma GEMM (64 x 128pad x 1024), 128
// CTAs, D2K=256 (only 4 chunk boundaries), 2-stage cp.async.
// Row stride 528B = 33x16B (odd -> ldmatrix conflict-free).
// =====================================================================
#define D2M 64
#define D2K 256
#define NCH2 (D_EMB / D2K)                  // 4
#define ROWB2 528                           // 256 fp16 (512B) + 16B pad
#define S2A 0
#define S2B (D2M * ROWB2)                   // 33792
#define STAGE2 ((D2M + 128) * ROWB2)        // 101376
#define DIST_SMEM (2 * STAGE2)              // 202752

__device__ __forceinline__ void copy_chunk2(uint32_t sb, int blockRow, int c, int tid)
{
    const size_t kb = (size_t)c * D2K * 2;   // byte offset within a row
    #pragma unroll
    for (int i = 0; i < 8; i++) {            // A: 64 rows x 32 segs = 2048
        const int id = tid + i * 256, rid = id >> 5, seg = id & 31;
        cp_async16(sb + S2A + rid * ROWB2 + seg * 16,
                   (const char*)g_Zh + ((size_t)(blockRow + rid) * D_EMB) * 2 + kb + seg * 16);
    }
    #pragma unroll
    for (int i = 0; i < 16; i++) {           // B: 128 rows x 32 segs = 4096
        const int id = tid + i * 256, rid = id >> 5, seg = id & 31;
        cp_async16(sb + S2B + rid * ROWB2 + seg * 16,
                   (const char*)g_Ph + ((size_t)rid * D_EMB) * 2 + kb + seg * 16);
    }
}

__global__ __launch_bounds__(256, 1)
void dist_mma_kernel(float* __restrict__ out)
{
    extern __shared__ char smem[];
    const uint32_t sbase = smem_u32(smem);
    const int tid = threadIdx.x;
    const int wid = tid >> 5;
    const int l   = tid & 31;
    const int warpM = wid >> 1;          // 0..3 -> 16-row strip
    const int warpN = wid & 1;           // 0..1 -> 64-col strip
    const int blockRow = blockIdx.x * D2M;

    const uint32_t aOff = (uint32_t)((warpM * 16 + (l & 15)) * ROWB2 + (l >> 4) * 16);
    uint32_t bOff[4];
    #pragma unroll
    for (int p = 0; p < 4; p++)
        bOff[p] = (uint32_t)(S2B + (warpN * 64 + p * 16 + ((l >> 4) & 1) * 8 + (l & 7)) * ROWB2
                             + ((l >> 3) & 1) * 16);

    float acc[8][4];
    #pragma unroll
    for (int nt = 0; nt < 8; nt++)
        #pragma unroll
        for (int r = 0; r < 4; r++) acc[nt][r] = 0.f;

    // prologue: 2 chunks in flight
    copy_chunk2(sbase, blockRow, 0, tid);          cp_commit();
    copy_chunk2(sbase + STAGE2, blockRow, 1, tid); cp_commit();

    for (int c = 0; c < NCH2; c++) {
        cp_wait1();            // chunk c resident (<=1 group outstanding)
        __syncthreads();       // everyone's copies visible

        const uint32_t st = sbase + (uint32_t)(c & 1) * STAGE2;
        #pragma unroll
        for (int ks = 0; ks < 16; ks++) {
            const uint32_t kb = ks * 32;
            uint32_t aF[4], bF[4][4];

            ldmx4(aF, st + aOff + kb);
            #pragma unroll
            for (int p = 0; p < 4; p++)   ldmx4(bF[p], st + bOff[p] + kb);

            #pragma unroll
            for (int p = 0; p < 4; p++) {
                mma_f16(acc[p * 2 + 0], aF, &bF[p][0]);
                mma_f16(acc[p * 2 + 1], aF, &bF[p][2]);
            }
        }

        __syncthreads();       // stage (c&1) fully consumed by all warps
        if (c + 2 < NCH2) copy_chunk2(sbase + (uint32_t)(c & 1) * STAGE2,
                                      blockRow, c + 2, tid);
        cp_commit();
    }

    // fused distance epilogue
    const float deps2 = (float)D_EMB * EPS_F * EPS_F;
    {
        const int r0 = blockRow + warpM * 16 + (l >> 2);
        const float q2a = g_q2[r0],     qsa = g_qs[r0];
        const float q2b = g_q2[r0 + 8], qsb = g_qs[r0 + 8];
        #pragma unroll
        for (int nt = 0; nt < 8; nt++) {
            const int c0 = warpN * 64 + nt * 8 + (l & 3) * 2;
            #pragma unroll
            for (int jj = 0; jj < 2; jj++) {
                const int c = c0 + jj;
                if (c < N_WAY) {
                    const float p2v = g_p2[c], psv = g_ps[c];
                    float sqa = q2a + p2v - 2.0f * acc[nt][jj]
                              + 2.0f * EPS_F * (qsa - psv) + deps2;
                    float sqb = q2b + p2v - 2.0f * acc[nt][2 + jj]
                              + 2.0f * EPS_F * (qsb - psv) + deps2;
                    out[(size_t)r0 * N_WAY + c]       = -sqrtf(fmaxf(sqa, 0.0f));
                    out[(size_t)(r0 + 8) * N_WAY + c] = -sqrtf(fmaxf(sqb, 0.0f));
                }
            }
        }
    }
}

// =====================================================================
// launch
// =====================================================================
extern "C" void kernel_launch(void* const* d_in, const int* in_sizes, int n_in,
                              void* d_out, int out_size)
{
    const float* support = (const float*)d_in[0];
    const int*   labels  = (const int*)  d_in[1];
    const float* query   = (const float*)d_in[2];
    const float* W       = (const float*)d_in[3];
    const float* b       = (const float*)d_in[4];
    float*       out     = (float*)d_out;

    cudaFuncSetAttribute(gemm_fp16,
                         cudaFuncAttributeMaxDynamicSharedMemorySize, GEMM_SMEM);
    cudaFuncSetAttribute(dist_mma_kernel,
                         cudaFuncAttributeMaxDynamicSharedMemorySize, DIST_SMEM);

    convert_W<<<dim3(F_IN / 32, D_EMB / 32), dim3(32, 8)>>>(W);

    gemm_fp16<<<dim3(D_EMB / GN, M_TOT / GM), 256, GEMM_SMEM>>>(query, support, b);

    proto_kernel<<<128, 1024>>>(labels);
    dist_mma_kernel<<<N_QUERY / D2M, 256, DIST_SMEM>>>(out);
}